// round 7
// baseline (speedup 1.0000x reference)
#include <cuda_runtime.h>
#include <cuda_bf16.h>
#include <cuda_fp16.h>
#include <cstdint>

#define Nn 16384
#define Ne 65536
#define Dd 64
#define Hh 128
#define Ll 3
#define Gg 512
#define Oo 128
#define KA 8320   // augmented K: 8192 (k,d) + 64 (S/b2) + 64 zero pad -> 65 tiles of 128

// ---------------- scratch -------------------------------------------------------
__device__ float g_x[Nn*Dd];
__device__ float g_h[Nn*Dd];
__device__ float g_a[(size_t)Ne*Hh];
__device__ __half g_T[(size_t)Nn*KA];                   // [dst][k*64+d | S | pad], fp16
__device__ __half g_w2aT_hi[(size_t)Ll*Dd*KA];          // [l][f][KA]
__device__ __half g_w2aT_lo[(size_t)Ll*Dd*KA];
__device__ __nv_bfloat16 g_w1t_hi[(size_t)Ll*Hh*Dd];    // [l][f=128][d=64]
__device__ __nv_bfloat16 g_w1t_lo[(size_t)Ll*Hh*Dd];
__device__ __nv_bfloat16 g_ea_hi[(size_t)Ne*Dd];
__device__ __nv_bfloat16 g_ea_lo[(size_t)Ne*Dd];
__device__ float g_num[Nn*Dd];
__device__ float g_deg[Nn];
__device__ float g_pool[Gg*Dd];
__device__ float g_cnt[Gg];
// CSR by dst
__device__ int g_dstcnt[Nn];
__device__ int g_cursor[Nn];
__device__ int g_rowptr[Nn + 1];
__device__ int g_esrc[Ne];
__device__ int g_eidx[Ne];

__device__ __forceinline__ float leaky(float v){ return v > 0.f ? v : 0.01f*v; }

// ---------------- init -----------------------------------------------------------
__global__ void k_init(const float* __restrict__ x){
    int i = blockIdx.x*blockDim.x + threadIdx.x;
    if(i < Nn*Dd){ g_x[i] = x[i]; g_num[i] = 0.f; }
    if(i < Gg*Dd) g_pool[i] = 0.f;
    if(i < Nn){ g_deg[i] = 0.f; g_dstcnt[i] = 0; g_cursor[i] = 0; }
    if(i < Gg)  g_cnt[i] = 0.f;
}

__global__ void k_degcnt(const int* __restrict__ ei, const int* __restrict__ batch){
    int i = blockIdx.x*blockDim.x + threadIdx.x;
    if(i < Ne){
        atomicAdd(&g_deg[ei[Ne + i]], 1.f);
        atomicAdd(&g_dstcnt[ei[Ne + i]], 1);
    }
    if(i < Nn) atomicAdd(&g_cnt[batch[i]], 1.f);
}

// single-block exclusive scan of g_dstcnt -> g_rowptr
__global__ void k_scan(){
    __shared__ int wsum[32];
    int t = threadIdx.x;
    int base = t*16;
    int c[16]; int s = 0;
    #pragma unroll
    for(int i = 0; i < 16; i++){ c[i] = g_dstcnt[base + i]; s += c[i]; }
    int lane = t & 31, w = t >> 5;
    int v = s;
    #pragma unroll
    for(int o = 1; o < 32; o <<= 1){ int u = __shfl_up_sync(~0u, v, o); if(lane >= o) v += u; }
    if(lane == 31) wsum[w] = v;
    __syncthreads();
    if(w == 0){
        int x = wsum[lane];
        #pragma unroll
        for(int o = 1; o < 32; o <<= 1){ int u = __shfl_up_sync(~0u, x, o); if(lane >= o) x += u; }
        wsum[lane] = x;
    }
    __syncthreads();
    int run = v - s + (w > 0 ? wsum[w-1] : 0);
    #pragma unroll
    for(int i = 0; i < 16; i++){ g_rowptr[base + i] = run; run += c[i]; }
    if(t == 1023) g_rowptr[Nn] = run;
}

__global__ void k_fill(const int* __restrict__ ei){
    int e = blockIdx.x*blockDim.x + threadIdx.x;
    if(e >= Ne) return;
    int dst = ei[Ne + e];
    int pos = g_rowptr[dst] + atomicAdd(&g_cursor[dst], 1);
    g_esrc[pos] = ei[e];
    g_eidx[pos] = e;
}

// ---------------- W2 augmented transpose, fp16 hi/lo: [l][f][KA] ------------------
// rows 0..8191: W2[l][k][d*64+f] -> [f][k*64+d]; rows 8192..8255: b2[l][d*64+f];
// rows 8256..8319: zero pad.
__global__ void k_prep_w2a(const float* __restrict__ W2, const float* __restrict__ b2){
    int idx = blockIdx.x*blockDim.x + threadIdx.x;
    if(idx >= Ll*Dd*KA) return;
    int l  = idx / (Dd*KA);
    int r  = idx % (Dd*KA);
    int f  = r / KA;
    int kk = r % KA;
    float v;
    if(kk < 8192){
        int k = kk >> 6, d = kk & 63;
        v = W2[((size_t)(l*Hh + k))*4096 + d*64 + f];
    } else if(kk < 8256){
        int d = kk - 8192;
        v = b2[(size_t)l*4096 + d*64 + f];
    } else v = 0.f;
    __half hi = __float2half(v);
    __half lo = __float2half(v - __half2float(hi));
    g_w2aT_hi[idx] = hi;
    g_w2aT_lo[idx] = lo;
}

// ---------------- W1 transpose + bf16 split: [l][d=64][f=128] -> [l][f][d] --------
__global__ void k_prep_w1(const float* __restrict__ W1){
    int idx = blockIdx.x*blockDim.x + threadIdx.x;
    if(idx >= Ll*Dd*Hh) return;
    int l = idx >> 13;
    int d = (idx >> 7) & 63;
    int f = idx & 127;
    float v = W1[idx];
    __nv_bfloat16 hi = __float2bfloat16(v);
    __nv_bfloat16 lo = __float2bfloat16(v - __bfloat162float(hi));
    size_t o = (size_t)l*Hh*Dd + f*64 + d;
    g_w1t_hi[o] = hi;
    g_w1t_lo[o] = lo;
}

// ---------------- edge_attr bf16 split (once) --------------------------------------
__global__ void k_prep_ea(const float* __restrict__ ea){
    int idx = blockIdx.x*blockDim.x + threadIdx.x;
    if(idx >= Ne*Dd) return;
    float v = ea[idx];
    __nv_bfloat16 hi = __float2bfloat16(v);
    g_ea_hi[idx] = hi;
    g_ea_lo[idx] = __float2bfloat16(v - __bfloat162float(hi));
}

// ---------------- h = leaky(LN(x)) -------------------------------------------------
__global__ void k_ln(const float* __restrict__ sc, const float* __restrict__ bi){
    int lane = threadIdx.x & 31, w = threadIdx.x >> 5;
    int n = blockIdx.x*8 + w;
    float v0 = g_x[n*64 + lane], v1 = g_x[n*64 + 32 + lane];
    float s = v0 + v1;
    #pragma unroll
    for(int o = 16; o; o >>= 1) s += __shfl_xor_sync(0xffffffffu, s, o);
    float mu = s * 0.015625f;
    float d0 = v0 - mu, d1 = v1 - mu;
    float q = d0*d0 + d1*d1;
    #pragma unroll
    for(int o = 16; o; o >>= 1) q += __shfl_xor_sync(0xffffffffu, q, o);
    float r = rsqrtf(q * 0.015625f + 1e-5f);
    g_h[n*64 + lane]      = leaky(d0*r*sc[lane]      + bi[lane]);
    g_h[n*64 + 32 + lane] = leaky(d1*r*sc[32 + lane] + bi[32 + lane]);
}

// ---------------- mma helpers (fragment mapping VALIDATED R5/R6) -------------------
#define BPAD 72
__device__ __forceinline__ void mma_bf16(float* c, const uint32_t* a, uint32_t b0, uint32_t b1){
    asm volatile(
        "mma.sync.aligned.m16n8k16.row.col.f32.bf16.bf16.f32 "
        "{%0,%1,%2,%3}, {%4,%5,%6,%7}, {%8,%9}, {%0,%1,%2,%3};"
        : "+f"(c[0]), "+f"(c[1]), "+f"(c[2]), "+f"(c[3])
        : "r"(a[0]), "r"(a[1]), "r"(a[2]), "r"(a[3]), "r"(b0), "r"(b1));
}
__device__ __forceinline__ void mma_f16(float* c, const uint32_t* a, uint32_t b0, uint32_t b1){
    asm volatile(
        "mma.sync.aligned.m16n8k16.row.col.f32.f16.f16.f32 "
        "{%0,%1,%2,%3}, {%4,%5,%6,%7}, {%8,%9}, {%0,%1,%2,%3};"
        : "+f"(c[0]), "+f"(c[1]), "+f"(c[2]), "+f"(c[3])
        : "r"(a[0]), "r"(a[1]), "r"(a[2]), "r"(a[3]), "r"(b0), "r"(b1));
}

// ---------------- a = leaky(ea @ W1 + b1) via mma (unchanged from R6) --------------
__global__ __launch_bounds__(256) void k_emlp_mma(int layer, const float* __restrict__ b1l){
    __shared__ __align__(16) __nv_bfloat16 Bh[128*BPAD];
    __shared__ __align__(16) __nv_bfloat16 Bl[128*BPAD];
    const __nv_bfloat16* w1h = g_w1t_hi + (size_t)layer*Hh*Dd;
    const __nv_bfloat16* w1l = g_w1t_lo + (size_t)layer*Hh*Dd;
    int tid = threadIdx.x, w = tid >> 5, lane = tid & 31;
    int g = lane >> 2, tq = lane & 3;
    int e0 = blockIdx.x * 128;
    int m0 = e0 + w*16;

    uint32_t ahi[4][4], alo[4][4];
    {
        int r0 = (m0 + g)*64, r1 = (m0 + g + 8)*64;
        #pragma unroll
        for(int ks = 0; ks < 4; ks++){
            int c0 = ks*16 + 2*tq, c1 = c0 + 8;
            ahi[ks][0] = *(const uint32_t*)&g_ea_hi[r0 + c0];
            ahi[ks][1] = *(const uint32_t*)&g_ea_hi[r1 + c0];
            ahi[ks][2] = *(const uint32_t*)&g_ea_hi[r0 + c1];
            ahi[ks][3] = *(const uint32_t*)&g_ea_hi[r1 + c1];
            alo[ks][0] = *(const uint32_t*)&g_ea_lo[r0 + c0];
            alo[ks][1] = *(const uint32_t*)&g_ea_lo[r1 + c0];
            alo[ks][2] = *(const uint32_t*)&g_ea_lo[r0 + c1];
            alo[ks][3] = *(const uint32_t*)&g_ea_lo[r1 + c1];
        }
    }
    {
        const uint4* sh = (const uint4*)w1h;
        const uint4* sl = (const uint4*)w1l;
        #pragma unroll
        for(int i = 0; i < 4; i++){
            int idx = i*256 + tid;
            int f = idx >> 3, u = idx & 7;
            *(uint4*)&Bh[f*BPAD + u*8] = sh[idx];
            *(uint4*)&Bl[f*BPAD + u*8] = sl[idx];
        }
    }
    __syncthreads();

    float acc[16][4];
    #pragma unroll
    for(int j = 0; j < 16; j++)
        #pragma unroll
        for(int i = 0; i < 4; i++) acc[j][i] = 0.f;

    #pragma unroll
    for(int ks = 0; ks < 4; ks++){
        int cb0 = ks*16 + 2*tq, cb1 = cb0 + 8;
        #pragma unroll
        for(int j = 0; j < 16; j++){
            int row = (j*8 + g)*BPAD;
            uint32_t bh0 = *(const uint32_t*)&Bh[row + cb0];
            uint32_t bh1 = *(const uint32_t*)&Bh[row + cb1];
            uint32_t bl0 = *(const uint32_t*)&Bl[row + cb0];
            uint32_t bl1 = *(const uint32_t*)&Bl[row + cb1];
            mma_bf16(acc[j], ahi[ks], bh0, bh1);
            mma_bf16(acc[j], ahi[ks], bl0, bl1);
            mma_bf16(acc[j], alo[ks], bh0, bh1);
        }
    }

    float* a0 = g_a + (size_t)(m0 + g)*128;
    float* a1 = g_a + (size_t)(m0 + g + 8)*128;
    #pragma unroll
    for(int j = 0; j < 16; j++){
        int c = j*8 + 2*tq;
        float2 bb = *(const float2*)&b1l[c];
        *(float2*)&a0[c] = make_float2(leaky(acc[j][0] + bb.x), leaky(acc[j][1] + bb.y));
        *(float2*)&a1[c] = make_float2(leaky(acc[j][2] + bb.x), leaky(acc[j][3] + bb.y));
    }
}

// ---------------- T builder: block per dst, register accumulators ------------------
// T[dst, k*64+d] = sum_{e->dst} a[e,k]*h[src,d];  T[dst, 8192+d] = sum h[src,d];
// tail 8256..8319 zero. Thread owns k0 = tid>>1, d-range (tid&1)*32..+32.
__global__ __launch_bounds__(256) void k_tbuild(){
    __shared__ float a_s[128];
    __shared__ float h_s[64];
    int n = blockIdx.x, tid = threadIdx.x;
    int beg = g_rowptr[n], end = g_rowptr[n+1];
    int k0 = tid >> 1, dbase = (tid & 1)*32;
    float acc[32];
    #pragma unroll
    for(int i = 0; i < 32; i++) acc[i] = 0.f;
    float s_acc = 0.f;

    for(int j = beg; j < end; j++){
        int src = g_esrc[j], eid = g_eidx[j];
        if(tid < 128)            a_s[tid]       = g_a[(size_t)eid*128 + tid];
        else if(tid < 192)       h_s[tid - 128] = g_h[src*64 + (tid - 128)];
        __syncthreads();
        float ak = a_s[k0];
        #pragma unroll
        for(int d = 0; d < 32; d++) acc[d] = fmaf(ak, h_s[dbase + d], acc[d]);
        if(tid < 64) s_acc += h_s[tid];
        __syncthreads();
    }

    // write 32 halves (64B, coalesced across thread pairs)
    uint32_t uu[16];
    #pragma unroll
    for(int i = 0; i < 16; i++){
        __half2 p = __floats2half2_rn(acc[2*i], acc[2*i+1]);
        uu[i] = *(uint32_t*)&p;
    }
    uint4* dst = (uint4*)(g_T + (size_t)n*KA + k0*64 + dbase);
    dst[0] = make_uint4(uu[0],  uu[1],  uu[2],  uu[3]);
    dst[1] = make_uint4(uu[4],  uu[5],  uu[6],  uu[7]);
    dst[2] = make_uint4(uu[8],  uu[9],  uu[10], uu[11]);
    dst[3] = make_uint4(uu[12], uu[13], uu[14], uu[15]);
    if(tid < 64){
        g_T[(size_t)n*KA + 8192 + tid] = __float2half(s_acc);
        g_T[(size_t)n*KA + 8256 + tid] = __float2half(0.f);
    }
}

// ---------------- num = T[16384 x KA] @ W2aug[KA x 64]  (fp16 A, 2-term split B) ---
#define GPAD 136   // 128 + 8 halves pad: bank-conflict-free fragment reads
__global__ __launch_bounds__(256, 2) void k_gemm(int layer){
    __shared__ __align__(16) __half Bh[64*GPAD];
    __shared__ __align__(16) __half Bl[64*GPAD];
    const __half* w2h = g_w2aT_hi + (size_t)layer*Dd*KA;
    const __half* w2l = g_w2aT_lo + (size_t)layer*Dd*KA;
    int tid = threadIdx.x, w = tid >> 5, lane = tid & 31;
    int g = lane >> 2, tq = lane & 3;
    int m0 = blockIdx.x*128 + w*16;
    const __half* Trow0 = g_T + (size_t)(m0 + g)*KA;
    const __half* Trow1 = g_T + (size_t)(m0 + g + 8)*KA;

    // prefetch B tile kt=0: per matrix 64 rows x 16 uint4; 4 per thread each
    uint4 pfh[4], pfl[4];
    #pragma unroll
    for(int i = 0; i < 4; i++){
        int idx = i*256 + tid;
        int f = idx >> 4, u = idx & 15;
        pfh[i] = *(const uint4*)(w2h + (size_t)f*KA + u*8);
        pfl[i] = *(const uint4*)(w2l + (size_t)f*KA + u*8);
    }

    float acc[8][4];
    #pragma unroll
    for(int j = 0; j < 8; j++)
        #pragma unroll
        for(int i = 0; i < 4; i++) acc[j][i] = 0.f;

    for(int kt = 0; kt < 65; kt++){
        __syncthreads();
        #pragma unroll
        for(int i = 0; i < 4; i++){
            int idx = i*256 + tid;
            int f = idx >> 4, u = idx & 15;
            *(uint4*)&Bh[f*GPAD + u*8] = pfh[i];
            *(uint4*)&Bl[f*GPAD + u*8] = pfl[i];
        }
        if(kt < 64){
            #pragma unroll
            for(int i = 0; i < 4; i++){
                int idx = i*256 + tid;
                int f = idx >> 4, u = idx & 15;
                pfh[i] = *(const uint4*)(w2h + (size_t)f*KA + (kt+1)*128 + u*8);
                pfl[i] = *(const uint4*)(w2l + (size_t)f*KA + (kt+1)*128 + u*8);
            }
        }
        __syncthreads();

        uint32_t a[8][4];
        #pragma unroll
        for(int ks = 0; ks < 8; ks++){
            int c0 = kt*128 + ks*16 + 2*tq, c1 = c0 + 8;
            a[ks][0] = *(const uint32_t*)&Trow0[c0];
            a[ks][1] = *(const uint32_t*)&Trow1[c0];
            a[ks][2] = *(const uint32_t*)&Trow0[c1];
            a[ks][3] = *(const uint32_t*)&Trow1[c1];
        }
        #pragma unroll
        for(int ks = 0; ks < 8; ks++){
            int cb0 = ks*16 + 2*tq, cb1 = cb0 + 8;
            #pragma unroll
            for(int j = 0; j < 8; j++){
                int row = (j*8 + g)*GPAD;
                uint32_t bh0 = *(const uint32_t*)&Bh[row + cb0];
                uint32_t bh1 = *(const uint32_t*)&Bh[row + cb1];
                uint32_t bl0 = *(const uint32_t*)&Bl[row + cb0];
                uint32_t bl1 = *(const uint32_t*)&Bl[row + cb1];
                mma_f16(acc[j], a[ks], bh0, bh1);
                mma_f16(acc[j], a[ks], bl0, bl1);
            }
        }
    }

    #pragma unroll
    for(int j = 0; j < 8; j++){
        int c = j*8 + 2*tq;
        *(float2*)&g_num[(m0 + g)*64 + c]     = make_float2(acc[j][0], acc[j][1]);
        *(float2*)&g_num[(m0 + g + 8)*64 + c] = make_float2(acc[j][2], acc[j][3]);
    }
}

// ---------------- shared 64x64 small GEMM with epilogues ---------------------------
// mode 1: g_x += g_num/max(deg,1) + g_h @ B + cb
// mode 2: pool[batch] += g_x @ B + bias (atomic)
__global__ __launch_bounds__(256) void k_nn64(const float* __restrict__ B,
                                              const float* __restrict__ bias,
                                              const float* __restrict__ cb,
                                              const int* __restrict__ batch,
                                              int mode){
    __shared__ float As[64][64];
    __shared__ float Bs[64][64];
    const float* A = (mode == 2) ? g_x : g_h;
    int tid = threadIdx.x;
    int n0 = blockIdx.x * 64;
    #pragma unroll
    for(int i = 0; i < 4; i++){
        int idx = i*256 + tid; int m = idx >> 4, d = (idx & 15) * 4;
        *(float4*)&As[m][d] = *(const float4*)&A[(size_t)(n0 + m)*64 + d];
        *(float4*)&Bs[m][d] = *(const float4*)&B[(size_t)m*64 + d];
    }
    __syncthreads();
    int tx = tid & 15, ty = tid >> 4;
    float acc[4][4];
    #pragma unroll
    for(int i = 0; i < 4; i++)
        #pragma unroll
        for(int j = 0; j < 4; j++) acc[i][j] = 0.f;

    #pragma unroll 4
    for(int d4 = 0; d4 < 64; d4 += 4){
        float4 a[4];
        #pragma unroll
        for(int i = 0; i < 4; i++) a[i] = *(float4*)&As[ty*4 + i][d4];
        #pragma unroll
        for(int dd = 0; dd < 4; dd++){
            float4 bv = *(float4*)&Bs[d4 + dd][tx*4];
            #pragma unroll
            for(int i = 0; i < 4; i++){
                float av = (dd==0)?a[i].x:(dd==1)?a[i].y:(dd==2)?a[i].z:a[i].w;
                acc[i][0] = fmaf(av, bv.x, acc[i][0]);
                acc[i][1] = fmaf(av, bv.y, acc[i][1]);
                acc[i][2] = fmaf(av, bv.z, acc[i][2]);
                acc[i][3] = fmaf(av, bv.w, acc[i][3]);
            }
        }
    }
    if(mode == 1){
        #pragma unroll
        for(int i = 0; i < 4; i++){
            int n = n0 + ty*4 + i;
            float inv = 1.f / fmaxf(g_deg[n], 1.f);
            #pragma unroll
            for(int j = 0; j < 4; j++){
                int idx = n*64 + tx*4 + j;
                g_x[idx] = g_x[idx] + g_num[idx]*inv + acc[i][j] + cb[tx*4 + j];
            }
        }
    } else {
        #pragma unroll
        for(int i = 0; i < 4; i++){
            int n = n0 + ty*4 + i;
            int b = batch[n];
            #pragma unroll
            for(int j = 0; j < 4; j++)
                atomicAdd(&g_pool[b*64 + tx*4 + j], acc[i][j] + bias[tx*4 + j]);
        }
    }
}

// ---------------- head -------------------------------------------------------------
__global__ void k_out(const float* __restrict__ oW, const float* __restrict__ ob,
                      float* __restrict__ out){
    __shared__ float p[64];
    int g = blockIdx.x, t = threadIdx.x;
    if(t < 64){
        float c = fmaxf(g_cnt[g], 1.f);
        p[t] = leaky(g_pool[g*64 + t] / c);
    }
    __syncthreads();
    float acc = ob[t];
    #pragma unroll 8
    for(int f = 0; f < 64; f++)
        acc = fmaf(p[f], oW[f*128 + t], acc);
    out[g*128 + t] = acc;
}

// ---------------- launch -------------------------------------------------------------
extern "C" void kernel_launch(void* const* d_in, const int* in_sizes, int n_in,
                              void* d_out, int out_size){
    const float* x    = (const float*)d_in[0];
    const int*   ei   = (const int*)  d_in[1];
    const float* ea   = (const float*)d_in[2];
    const int*   batch= (const int*)  d_in[3];
    const float* lns  = (const float*)d_in[4];
    const float* lnb  = (const float*)d_in[5];
    const float* W1   = (const float*)d_in[6];
    const float* b1   = (const float*)d_in[7];
    const float* W2   = (const float*)d_in[8];
    const float* b2   = (const float*)d_in[9];
    const float* root = (const float*)d_in[10];
    const float* cb   = (const float*)d_in[11];
    const float* dW   = (const float*)d_in[12];
    const float* db   = (const float*)d_in[13];
    const float* oW   = (const float*)d_in[14];
    const float* ob   = (const float*)d_in[15];
    float* out = (float*)d_out;

    k_init<<<(Nn*Dd + 255)/256, 256>>>(x);
    k_degcnt<<<(Ne + 255)/256, 256>>>(ei, batch);
    k_scan<<<1, 1024>>>();
    k_fill<<<(Ne + 255)/256, 256>>>(ei);
    k_prep_w2a<<<(Ll*Dd*KA + 255)/256, 256>>>(W2, b2);
    k_prep_w1<<<(Ll*Dd*Hh + 255)/256, 256>>>(W1);
    k_prep_ea<<<(Ne*Dd + 255)/256, 256>>>(ea);

    for(int l = 0; l < Ll; l++){
        k_ln<<<Nn/8, 256>>>(lns + l*64, lnb + l*64);
        k_emlp_mma<<<Ne/128, 256>>>(l, b1 + (size_t)l*128);
        k_tbuild<<<Nn, 256>>>();
        k_gemm<<<Nn/128, 256>>>(l);
        k_nn64<<<Nn/64, 256>>>(root + (size_t)l*4096, nullptr, cb + (size_t)l*64, nullptr, 1);
    }

    k_nn64<<<Nn/64, 256>>>(dW, db, nullptr, batch, 2);  // dense + pool
    k_out<<<Gg, 128>>>(oW, ob, out);
}

// round 8
// speedup vs baseline: 1.3201x; 1.3201x over previous
#include <cuda_runtime.h>
#include <cuda_bf16.h>
#include <cuda_fp16.h>
#include <cstdint>

#define Nn 16384
#define Ne 65536
#define Dd 64
#define Hh 128
#define Ll 3
#define Gg 512
#define Oo 128

// ---------------- scratch -------------------------------------------------------
__device__ float g_x[Nn*Dd];
__device__ float g_h[Nn*Dd];
__device__ __nv_bfloat16 g_h_hi[Nn*Dd];
__device__ __nv_bfloat16 g_h_lo[Nn*Dd];
__device__ float g_y2[Nn*Dd];
__device__ float g_a[(size_t)Ne*Hh];
__device__ __half g_Q[(size_t)Nn*Hh*Dd];                 // [n][k][f], fp16, 256 MB
__device__ __nv_bfloat16 g_w2t_hi[(size_t)Ll*Hh*Dd*Dd]; // [l][k][f][d]
__device__ __nv_bfloat16 g_w2t_lo[(size_t)Ll*Hh*Dd*Dd];
__device__ __nv_bfloat16 g_w1t_hi[(size_t)Ll*Hh*Dd];    // [l][f=128][d=64]
__device__ __nv_bfloat16 g_w1t_lo[(size_t)Ll*Hh*Dd];
__device__ __nv_bfloat16 g_ea_hi[(size_t)Ne*Dd];
__device__ __nv_bfloat16 g_ea_lo[(size_t)Ne*Dd];
__device__ float g_num[Nn*Dd];
__device__ float g_deg[Nn];
__device__ float g_pool[Gg*Dd];
__device__ float g_cnt[Gg];
// CSR by src
__device__ int g_srccnt[Nn];
__device__ int g_cursor[Nn];
__device__ int g_rowptr[Nn + 1];
__device__ int g_edst[Ne];
__device__ int g_eidx[Ne];

__device__ __forceinline__ float leaky(float v){ return v > 0.f ? v : 0.01f*v; }

// ---------------- merged weight/edge prep (one launch slot) -----------------------
__global__ void k_prep(const float* __restrict__ W2, const float* __restrict__ W1,
                       const float* __restrict__ ea){
    int idx = blockIdx.x*blockDim.x + threadIdx.x;
    // edge_attr split: idx in [0, Ne*Dd)
    if(idx < Ne*Dd){
        float v = ea[idx];
        __nv_bfloat16 hi = __float2bfloat16(v);
        g_ea_hi[idx] = hi;
        g_ea_lo[idx] = __float2bfloat16(v - __bfloat162float(hi));
    }
    // W2 transpose+split: [l][k][d][f] -> [l][k][f][d]
    if(idx < Ll*Hh*Dd*Dd){
        int lk = idx >> 12;
        int d = (idx >> 6) & 63;
        int f = idx & 63;
        float v = W2[idx];
        __nv_bfloat16 hi = __float2bfloat16(v);
        __nv_bfloat16 lo = __float2bfloat16(v - __bfloat162float(hi));
        size_t o = (size_t)lk*4096 + f*64 + d;
        g_w2t_hi[o] = hi;
        g_w2t_lo[o] = lo;
    }
    // W1 transpose+split: [l][d][f=128] -> [l][f][d]
    if(idx < Ll*Dd*Hh){
        int l = idx >> 13;
        int d = (idx >> 7) & 63;
        int f = idx & 127;
        float v = W1[idx];
        __nv_bfloat16 hi = __float2bfloat16(v);
        __nv_bfloat16 lo = __float2bfloat16(v - __bfloat162float(hi));
        size_t o = (size_t)l*Hh*Dd + f*64 + d;
        g_w1t_hi[o] = hi;
        g_w1t_lo[o] = lo;
    }
}

// ---------------- init -----------------------------------------------------------
__global__ void k_init(const float* __restrict__ x){
    int i = blockIdx.x*blockDim.x + threadIdx.x;
    if(i < Nn*Dd){ g_x[i] = x[i]; g_num[i] = 0.f; }
    if(i < Gg*Dd) g_pool[i] = 0.f;
    if(i < Nn){ g_deg[i] = 0.f; g_srccnt[i] = 0; g_cursor[i] = 0; }
    if(i < Gg)  g_cnt[i] = 0.f;
}

__global__ void k_degcnt(const int* __restrict__ ei, const int* __restrict__ batch){
    int i = blockIdx.x*blockDim.x + threadIdx.x;
    if(i < Ne){
        atomicAdd(&g_deg[ei[Ne + i]], 1.f);
        atomicAdd(&g_srccnt[ei[i]], 1);
    }
    if(i < Nn) atomicAdd(&g_cnt[batch[i]], 1.f);
}

// single-block exclusive scan of g_srccnt -> g_rowptr
__global__ void k_scan(){
    __shared__ int wsum[32];
    int t = threadIdx.x;
    int base = t*16;
    int c[16]; int s = 0;
    #pragma unroll
    for(int i = 0; i < 16; i++){ c[i] = g_srccnt[base + i]; s += c[i]; }
    int lane = t & 31, w = t >> 5;
    int v = s;
    #pragma unroll
    for(int o = 1; o < 32; o <<= 1){ int u = __shfl_up_sync(~0u, v, o); if(lane >= o) v += u; }
    if(lane == 31) wsum[w] = v;
    __syncthreads();
    if(w == 0){
        int x = wsum[lane];
        #pragma unroll
        for(int o = 1; o < 32; o <<= 1){ int u = __shfl_up_sync(~0u, x, o); if(lane >= o) x += u; }
        wsum[lane] = x;
    }
    __syncthreads();
    int run = v - s + (w > 0 ? wsum[w-1] : 0);
    #pragma unroll
    for(int i = 0; i < 16; i++){ g_rowptr[base + i] = run; run += c[i]; }
    if(t == 1023) g_rowptr[Nn] = run;
}

__global__ void k_fill(const int* __restrict__ ei){
    int e = blockIdx.x*blockDim.x + threadIdx.x;
    if(e >= Ne) return;
    int src = ei[e];
    int pos = g_rowptr[src] + atomicAdd(&g_cursor[src], 1);
    g_edst[pos] = ei[Ne + e];
    g_eidx[pos] = e;
}

// ---------------- h = leaky(LN(x)); also emit bf16 hi/lo --------------------------
__global__ void k_ln(const float* __restrict__ sc, const float* __restrict__ bi){
    int lane = threadIdx.x & 31, w = threadIdx.x >> 5;
    int n = blockIdx.x*8 + w;
    float v0 = g_x[n*64 + lane], v1 = g_x[n*64 + 32 + lane];
    float s = v0 + v1;
    #pragma unroll
    for(int o = 16; o; o >>= 1) s += __shfl_xor_sync(0xffffffffu, s, o);
    float mu = s * 0.015625f;
    float d0 = v0 - mu, d1 = v1 - mu;
    float q = d0*d0 + d1*d1;
    #pragma unroll
    for(int o = 16; o; o >>= 1) q += __shfl_xor_sync(0xffffffffu, q, o);
    float r = rsqrtf(q * 0.015625f + 1e-5f);
    float h0 = leaky(d0*r*sc[lane]      + bi[lane]);
    float h1 = leaky(d1*r*sc[32 + lane] + bi[32 + lane]);
    g_h[n*64 + lane]      = h0;
    g_h[n*64 + 32 + lane] = h1;
    __nv_bfloat16 h0h = __float2bfloat16(h0), h1h = __float2bfloat16(h1);
    g_h_hi[n*64 + lane]      = h0h;
    g_h_hi[n*64 + 32 + lane] = h1h;
    g_h_lo[n*64 + lane]      = __float2bfloat16(h0 - __bfloat162float(h0h));
    g_h_lo[n*64 + 32 + lane] = __float2bfloat16(h1 - __bfloat162float(h1h));
}

// ---------------- mma helper (fragment mapping VALIDATED R5/R6) --------------------
#define BPAD 72
__device__ __forceinline__ void mma_bf16(float* c, const uint32_t* a, uint32_t b0, uint32_t b1){
    asm volatile(
        "mma.sync.aligned.m16n8k16.row.col.f32.bf16.bf16.f32 "
        "{%0,%1,%2,%3}, {%4,%5,%6,%7}, {%8,%9}, {%0,%1,%2,%3};"
        : "+f"(c[0]), "+f"(c[1]), "+f"(c[2]), "+f"(c[3])
        : "r"(a[0]), "r"(a[1]), "r"(a[2]), "r"(a[3]), "r"(b0), "r"(b1));
}

__device__ __forceinline__ void load_a_frags(const __nv_bfloat16* ph, const __nv_bfloat16* pl,
                                             int m0, int g, int tq,
                                             uint32_t ahi[4][4], uint32_t alo[4][4]){
    int r0 = (m0 + g)*64, r1 = (m0 + g + 8)*64;
    #pragma unroll
    for(int ks = 0; ks < 4; ks++){
        int c0 = ks*16 + 2*tq, c1 = c0 + 8;
        ahi[ks][0] = *(const uint32_t*)&ph[r0 + c0];
        ahi[ks][1] = *(const uint32_t*)&ph[r1 + c0];
        ahi[ks][2] = *(const uint32_t*)&ph[r0 + c1];
        ahi[ks][3] = *(const uint32_t*)&ph[r1 + c1];
        alo[ks][0] = *(const uint32_t*)&pl[r0 + c0];
        alo[ks][1] = *(const uint32_t*)&pl[r1 + c0];
        alo[ks][2] = *(const uint32_t*)&pl[r0 + c1];
        alo[ks][3] = *(const uint32_t*)&pl[r1 + c1];
    }
}

// ---------------- a = leaky(ea @ W1 + b1) via mma (unchanged, validated R6) --------
__global__ __launch_bounds__(256) void k_emlp_mma(int layer, const float* __restrict__ b1l){
    __shared__ __align__(16) __nv_bfloat16 Bh[128*BPAD];
    __shared__ __align__(16) __nv_bfloat16 Bl[128*BPAD];
    const __nv_bfloat16* w1h = g_w1t_hi + (size_t)layer*Hh*Dd;
    const __nv_bfloat16* w1l = g_w1t_lo + (size_t)layer*Hh*Dd;
    int tid = threadIdx.x, w = tid >> 5, lane = tid & 31;
    int g = lane >> 2, tq = lane & 3;
    int e0 = blockIdx.x * 128;
    int m0 = e0 + w*16;

    uint32_t ahi[4][4], alo[4][4];
    load_a_frags(g_ea_hi, g_ea_lo, m0, g, tq, ahi, alo);
    {
        const uint4* sh = (const uint4*)w1h;
        const uint4* sl = (const uint4*)w1l;
        #pragma unroll
        for(int i = 0; i < 4; i++){
            int idx = i*256 + tid;
            int f = idx >> 3, u = idx & 7;
            *(uint4*)&Bh[f*BPAD + u*8] = sh[idx];
            *(uint4*)&Bl[f*BPAD + u*8] = sl[idx];
        }
    }
    __syncthreads();

    float acc[16][4];
    #pragma unroll
    for(int j = 0; j < 16; j++)
        #pragma unroll
        for(int i = 0; i < 4; i++) acc[j][i] = 0.f;

    #pragma unroll
    for(int ks = 0; ks < 4; ks++){
        int cb0 = ks*16 + 2*tq, cb1 = cb0 + 8;
        #pragma unroll
        for(int j = 0; j < 16; j++){
            int row = (j*8 + g)*BPAD;
            uint32_t bh0 = *(const uint32_t*)&Bh[row + cb0];
            uint32_t bh1 = *(const uint32_t*)&Bh[row + cb1];
            uint32_t bl0 = *(const uint32_t*)&Bl[row + cb0];
            uint32_t bl1 = *(const uint32_t*)&Bl[row + cb1];
            mma_bf16(acc[j], ahi[ks], bh0, bh1);
            mma_bf16(acc[j], ahi[ks], bl0, bl1);
            mma_bf16(acc[j], alo[ks], bh0, bh1);
        }
    }

    float* a0 = g_a + (size_t)(m0 + g)*128;
    float* a1 = g_a + (size_t)(m0 + g + 8)*128;
    #pragma unroll
    for(int j = 0; j < 16; j++){
        int c = j*8 + 2*tq;
        float2 bb = *(const float2*)&b1l[c];
        *(float2*)&a0[c] = make_float2(leaky(acc[j][0] + bb.x), leaky(acc[j][1] + bb.y));
        *(float2*)&a1[c] = make_float2(leaky(acc[j][2] + bb.x), leaky(acc[j][3] + bb.y));
    }
}

// ---------------- Q via mma (unchanged, validated R6; fp16 store) ------------------
__global__ __launch_bounds__(256) void k_q_mma(int layer){
    __shared__ __align__(16) __nv_bfloat16 Bh[64*BPAD];
    __shared__ __align__(16) __nv_bfloat16 Bl[64*BPAD];
    const __nv_bfloat16* w2h = g_w2t_hi + (size_t)layer*Hh*4096;
    const __nv_bfloat16* w2l = g_w2t_lo + (size_t)layer*Hh*4096;
    int tid = threadIdx.x, w = tid >> 5, lane = tid & 31;
    int g = lane >> 2, tq = lane & 3;
    int n0 = blockIdx.x * 128;
    int m0 = n0 + w*16;

    uint32_t ahi[4][4], alo[4][4];
    load_a_frags(g_h_hi, g_h_lo, m0, g, tq, ahi, alo);

    int kbase = blockIdx.y*8;
    uint4 pf_h0, pf_h1, pf_l0, pf_l1;
    {
        const uint4* sh = (const uint4*)(w2h + (size_t)kbase*4096);
        const uint4* sl = (const uint4*)(w2l + (size_t)kbase*4096);
        pf_h0 = sh[tid]; pf_h1 = sh[256 + tid];
        pf_l0 = sl[tid]; pf_l1 = sl[256 + tid];
    }
    int f0 = tid >> 3,         u0 = tid & 7;
    int f1 = (256 + tid) >> 3, u1 = tid & 7;

    for(int kk = 0; kk < 8; kk++){
        int k = kbase + kk;
        __syncthreads();
        *(uint4*)&Bh[f0*BPAD + u0*8] = pf_h0;
        *(uint4*)&Bh[f1*BPAD + u1*8] = pf_h1;
        *(uint4*)&Bl[f0*BPAD + u0*8] = pf_l0;
        *(uint4*)&Bl[f1*BPAD + u1*8] = pf_l1;
        if(kk < 7){
            const uint4* sh = (const uint4*)(w2h + (size_t)(k + 1)*4096);
            const uint4* sl = (const uint4*)(w2l + (size_t)(k + 1)*4096);
            pf_h0 = sh[tid]; pf_h1 = sh[256 + tid];
            pf_l0 = sl[tid]; pf_l1 = sl[256 + tid];
        }
        __syncthreads();

        float acc[8][4];
        #pragma unroll
        for(int j = 0; j < 8; j++)
            #pragma unroll
            for(int i = 0; i < 4; i++) acc[j][i] = 0.f;

        #pragma unroll
        for(int ks = 0; ks < 4; ks++){
            int cb0 = ks*16 + 2*tq, cb1 = cb0 + 8;
            #pragma unroll
            for(int j = 0; j < 8; j++){
                int row = (j*8 + g)*BPAD;
                uint32_t bh0 = *(const uint32_t*)&Bh[row + cb0];
                uint32_t bh1 = *(const uint32_t*)&Bh[row + cb1];
                uint32_t bl0 = *(const uint32_t*)&Bl[row + cb0];
                uint32_t bl1 = *(const uint32_t*)&Bl[row + cb1];
                mma_bf16(acc[j], ahi[ks], bh0, bh1);
                mma_bf16(acc[j], ahi[ks], bl0, bl1);
                mma_bf16(acc[j], alo[ks], bh0, bh1);
            }
        }

        __half* q0 = g_Q + ((size_t)(m0 + g)*128 + k)*64;
        __half* q1 = g_Q + ((size_t)(m0 + g + 8)*128 + k)*64;
        #pragma unroll
        for(int j = 0; j < 8; j++){
            int c = j*8 + 2*tq;
            *(__half2*)&q0[c] = __floats2half2_rn(acc[j][0], acc[j][1]);
            *(__half2*)&q1[c] = __floats2half2_rn(acc[j][2], acc[j][3]);
        }
    }
}

// ---------------- messages v3: fp16 smem Q, 8 edges/batch, f-pair lanes ------------
__global__ __launch_bounds__(256) void k_msg2(){
    __shared__ __align__(16) __half Qs[8192];   // [k][f] fp16, 16KB
    __shared__ float as[8][128];
    __shared__ float y2s[64];
    int n = blockIdx.x;
    int beg = g_rowptr[n], end = g_rowptr[n+1];
    if(beg == end) return;
    int tid = threadIdx.x;
    // stage Q[n] raw: 1024 uint4, 4 per thread
    const uint4* qsrc = (const uint4*)(g_Q + (size_t)n*8192);
    uint4* qd = (uint4*)Qs;
    #pragma unroll
    for(int i = 0; i < 4; i++) qd[i*256 + tid] = qsrc[i*256 + tid];
    if(tid < 64) y2s[tid] = g_y2[n*64 + tid];
    __syncthreads();
    int g = tid >> 5, lane = tid & 31;             // 8 edge slots x 32 lanes
    const __half2* Q2 = (const __half2*)Qs;        // [k][f2]: k*32 + lane
    for(int base = beg; base < end; base += 8){
        #pragma unroll
        for(int i = 0; i < 4; i++){
            int idx = i*256 + tid;
            int el = idx >> 7, k = idx & 127;
            int j = base + el;
            if(j < end) as[el][k] = g_a[(size_t)g_eidx[j]*128 + k];
        }
        __syncthreads();
        int j = base + g;
        if(j < end){
            int dst = g_edst[j];
            float accx = y2s[2*lane], accy = y2s[2*lane + 1];
            #pragma unroll 8
            for(int k4 = 0; k4 < 128; k4 += 4){
                float4 av = *(const float4*)&as[g][k4];
                float2 q0 = __half22float2(Q2[(k4+0)*32 + lane]);
                float2 q1 = __half22float2(Q2[(k4+1)*32 + lane]);
                float2 q2 = __half22float2(Q2[(k4+2)*32 + lane]);
                float2 q3 = __half22float2(Q2[(k4+3)*32 + lane]);
                accx = fmaf(av.x, q0.x, accx); accy = fmaf(av.x, q0.y, accy);
                accx = fmaf(av.y, q1.x, accx); accy = fmaf(av.y, q1.y, accy);
                accx = fmaf(av.z, q2.x, accx); accy = fmaf(av.z, q2.y, accy);
                accx = fmaf(av.w, q3.x, accx); accy = fmaf(av.w, q3.y, accy);
            }
            atomicAdd(&g_num[dst*64 + 2*lane],     accx);
            atomicAdd(&g_num[dst*64 + 2*lane + 1], accy);
        }
        __syncthreads();
    }
}

// ---------------- shared 64x64 small GEMM with three epilogues ---------------------
__global__ __launch_bounds__(256) void k_nn64(const float* __restrict__ B,
                                              const float* __restrict__ bias,
                                              const float* __restrict__ cb,
                                              const int* __restrict__ batch,
                                              int mode){
    __shared__ float As[64][64];
    __shared__ float Bs[64][64];
    const float* A = (mode == 2) ? g_x : g_h;
    int tid = threadIdx.x;
    int n0 = blockIdx.x * 64;
    #pragma unroll
    for(int i = 0; i < 4; i++){
        int idx = i*256 + tid; int m = idx >> 4, d = (idx & 15) * 4;
        *(float4*)&As[m][d] = *(const float4*)&A[(size_t)(n0 + m)*64 + d];
        *(float4*)&Bs[m][d] = *(const float4*)&B[(size_t)m*64 + d];
    }
    __syncthreads();
    int tx = tid & 15, ty = tid >> 4;
    float acc[4][4];
    #pragma unroll
    for(int i = 0; i < 4; i++)
        #pragma unroll
        for(int j = 0; j < 4; j++) acc[i][j] = 0.f;

    #pragma unroll 4
    for(int d4 = 0; d4 < 64; d4 += 4){
        float4 a[4];
        #pragma unroll
        for(int i = 0; i < 4; i++) a[i] = *(float4*)&As[ty*4 + i][d4];
        #pragma unroll
        for(int dd = 0; dd < 4; dd++){
            float4 bv = *(float4*)&Bs[d4 + dd][tx*4];
            #pragma unroll
            for(int i = 0; i < 4; i++){
                float av = (dd==0)?a[i].x:(dd==1)?a[i].y:(dd==2)?a[i].z:a[i].w;
                acc[i][0] = fmaf(av, bv.x, acc[i][0]);
                acc[i][1] = fmaf(av, bv.y, acc[i][1]);
                acc[i][2] = fmaf(av, bv.z, acc[i][2]);
                acc[i][3] = fmaf(av, bv.w, acc[i][3]);
            }
        }
    }
    if(mode == 0){
        #pragma unroll
        for(int i = 0; i < 4; i++){
            float4 o; o.x = acc[i][0]; o.y = acc[i][1]; o.z = acc[i][2]; o.w = acc[i][3];
            *(float4*)&g_y2[(size_t)(n0 + ty*4 + i)*64 + tx*4] = o;
        }
    } else if(mode == 1){
        #pragma unroll
        for(int i = 0; i < 4; i++){
            int n = n0 + ty*4 + i;
            float inv = 1.f / fmaxf(g_deg[n], 1.f);
            #pragma unroll
            for(int j = 0; j < 4; j++){
                int idx = n*64 + tx*4 + j;
                float v = g_x[idx] + g_num[idx]*inv + acc[i][j] + cb[tx*4 + j];
                g_x[idx] = v;
                g_num[idx] = 0.f;
            }
        }
    } else {
        #pragma unroll
        for(int i = 0; i < 4; i++){
            int n = n0 + ty*4 + i;
            int b = batch[n];
            #pragma unroll
            for(int j = 0; j < 4; j++)
                atomicAdd(&g_pool[b*64 + tx*4 + j], acc[i][j] + bias[tx*4 + j]);
        }
    }
}

// ---------------- head -------------------------------------------------------------
__global__ void k_out(const float* __restrict__ oW, const float* __restrict__ ob,
                      float* __restrict__ out){
    __shared__ float p[64];
    int g = blockIdx.x, t = threadIdx.x;
    if(t < 64){
        float c = fmaxf(g_cnt[g], 1.f);
        p[t] = leaky(g_pool[g*64 + t] / c);
    }
    __syncthreads();
    float acc = ob[t];
    #pragma unroll 8
    for(int f = 0; f < 64; f++)
        acc = fmaf(p[f], oW[f*128 + t], acc);
    out[g*128 + t] = acc;
}

// ---------------- launch -------------------------------------------------------------
extern "C" void kernel_launch(void* const* d_in, const int* in_sizes, int n_in,
                              void* d_out, int out_size){
    const float* x    = (const float*)d_in[0];
    const int*   ei   = (const int*)  d_in[1];
    const float* ea   = (const float*)d_in[2];
    const int*   batch= (const int*)  d_in[3];
    const float* lns  = (const float*)d_in[4];
    const float* lnb  = (const float*)d_in[5];
    const float* W1   = (const float*)d_in[6];
    const float* b1   = (const float*)d_in[7];
    const float* W2   = (const float*)d_in[8];
    const float* b2   = (const float*)d_in[9];
    const float* root = (const float*)d_in[10];
    const float* cb   = (const float*)d_in[11];
    const float* dW   = (const float*)d_in[12];
    const float* db   = (const float*)d_in[13];
    const float* oW   = (const float*)d_in[14];
    const float* ob   = (const float*)d_in[15];
    float* out = (float*)d_out;

    dim3 gq(Nn/128, Hh/8);

    // Order chosen so launch index 3 (the one ncu captures) = k_q_mma(layer 0).
    k_prep<<<(Ne*Dd + 255)/256, 256>>>(W2, W1, ea);            // 0
    k_init<<<(Nn*Dd + 255)/256, 256>>>(x);                     // 1
    k_ln<<<Nn/8, 256>>>(lns, lnb);                             // 2
    k_q_mma<<<gq, 256>>>(0);                                   // 3  <- profiled
    k_degcnt<<<(Ne + 255)/256, 256>>>(ei, batch);              // 4
    k_scan<<<1, 1024>>>();                                     // 5
    k_fill<<<(Ne + 255)/256, 256>>>(ei);                       // 6
    k_emlp_mma<<<Ne/128, 256>>>(0, b1);                        // 7
    k_nn64<<<Nn/64, 256>>>(b2, nullptr, nullptr, nullptr, 0);  // 8: y2 = h@B2
    k_msg2<<<Nn, 256>>>();                                     // 9
    k_nn64<<<Nn/64, 256>>>(root, nullptr, cb, nullptr, 1);     // 10

    for(int l = 1; l < Ll; l++){
        k_ln<<<Nn/8, 256>>>(lns + l*64, lnb + l*64);
        k_emlp_mma<<<Ne/128, 256>>>(l, b1 + (size_t)l*128);
        k_nn64<<<Nn/64, 256>>>(b2 + (size_t)l*4096, nullptr, nullptr, nullptr, 0);
        k_q_mma<<<gq, 256>>>(l);
        k_msg2<<<Nn, 256>>>();
        k_nn64<<<Nn/64, 256>>>(root + (size_t)l*4096, nullptr, cb + (size_t)l*64, nullptr, 1);
    }

    k_nn64<<<Nn/64, 256>>>(dW, db, nullptr, batch, 2);  // dense + pool
    k_out<<<Gg, 128>>>(oW, ob, out);
}

// round 9
// speedup vs baseline: 1.3766x; 1.0428x over previous
#include <cuda_runtime.h>
#include <cuda_bf16.h>
#include <cuda_fp16.h>
#include <cstdint>

#define Nn 16384
#define Ne 65536
#define Dd 64
#define Hh 128
#define Ll 3
#define Gg 512
#define Oo 128

// ---------------- scratch -------------------------------------------------------
__device__ float g_x[Nn*Dd];
__device__ float g_h[Nn*Dd];
__device__ __nv_bfloat16 g_h_hi[Nn*Dd];
__device__ __nv_bfloat16 g_h_lo[Nn*Dd];
__device__ float g_y2[Nn*Dd];
__device__ float g_a[(size_t)Ne*Hh];
__device__ __half g_Q[(size_t)Nn*Hh*Dd];                 // [n][k][f], fp16, 256 MB
__device__ __nv_bfloat16 g_w2t_hi[(size_t)Ll*Hh*Dd*Dd]; // [l][k][f][d]
__device__ __nv_bfloat16 g_w2t_lo[(size_t)Ll*Hh*Dd*Dd];
__device__ __nv_bfloat16 g_w1t_hi[(size_t)Ll*Hh*Dd];    // [l][f=128][d=64]
__device__ __nv_bfloat16 g_w1t_lo[(size_t)Ll*Hh*Dd];
__device__ __nv_bfloat16 g_ea_hi[(size_t)Ne*Dd];
__device__ __nv_bfloat16 g_ea_lo[(size_t)Ne*Dd];
__device__ float g_num[Nn*Dd];
__device__ float g_deg[Nn];
__device__ float g_pool[Gg*Dd];
__device__ float g_cnt[Gg];
// CSR by src
__device__ int g_srccnt[Nn];
__device__ int g_cursor[Nn];
__device__ int g_rowptr[Nn + 1];
__device__ int g_edst[Ne];
__device__ int g_eidx[Ne];

__device__ __forceinline__ float leaky(float v){ return v > 0.f ? v : 0.01f*v; }

// ---------------- merged weight/edge prep (one launch slot) -----------------------
__global__ void k_prep(const float* __restrict__ W2, const float* __restrict__ W1,
                       const float* __restrict__ ea){
    int idx = blockIdx.x*blockDim.x + threadIdx.x;
    if(idx < Ne*Dd){
        float v = ea[idx];
        __nv_bfloat16 hi = __float2bfloat16(v);
        g_ea_hi[idx] = hi;
        g_ea_lo[idx] = __float2bfloat16(v - __bfloat162float(hi));
    }
    if(idx < Ll*Hh*Dd*Dd){
        int lk = idx >> 12;
        int d = (idx >> 6) & 63;
        int f = idx & 63;
        float v = W2[idx];
        __nv_bfloat16 hi = __float2bfloat16(v);
        __nv_bfloat16 lo = __float2bfloat16(v - __bfloat162float(hi));
        size_t o = (size_t)lk*4096 + f*64 + d;
        g_w2t_hi[o] = hi;
        g_w2t_lo[o] = lo;
    }
    if(idx < Ll*Dd*Hh){
        int l = idx >> 13;
        int d = (idx >> 7) & 63;
        int f = idx & 127;
        float v = W1[idx];
        __nv_bfloat16 hi = __float2bfloat16(v);
        __nv_bfloat16 lo = __float2bfloat16(v - __bfloat162float(hi));
        size_t o = (size_t)l*Hh*Dd + f*64 + d;
        g_w1t_hi[o] = hi;
        g_w1t_lo[o] = lo;
    }
}

// ---------------- init -----------------------------------------------------------
__global__ void k_init(const float* __restrict__ x){
    int i = blockIdx.x*blockDim.x + threadIdx.x;
    if(i < Nn*Dd){ g_x[i] = x[i]; g_num[i] = 0.f; }
    if(i < Gg*Dd) g_pool[i] = 0.f;
    if(i < Nn){ g_deg[i] = 0.f; g_srccnt[i] = 0; g_cursor[i] = 0; }
    if(i < Gg)  g_cnt[i] = 0.f;
}

__global__ void k_degcnt(const int* __restrict__ ei, const int* __restrict__ batch){
    int i = blockIdx.x*blockDim.x + threadIdx.x;
    if(i < Ne){
        atomicAdd(&g_deg[ei[Ne + i]], 1.f);
        atomicAdd(&g_srccnt[ei[i]], 1);
    }
    if(i < Nn) atomicAdd(&g_cnt[batch[i]], 1.f);
}

// single-block exclusive scan of g_srccnt -> g_rowptr
__global__ void k_scan(){
    __shared__ int wsum[32];
    int t = threadIdx.x;
    int base = t*16;
    int c[16]; int s = 0;
    #pragma unroll
    for(int i = 0; i < 16; i++){ c[i] = g_srccnt[base + i]; s += c[i]; }
    int lane = t & 31, w = t >> 5;
    int v = s;
    #pragma unroll
    for(int o = 1; o < 32; o <<= 1){ int u = __shfl_up_sync(~0u, v, o); if(lane >= o) v += u; }
    if(lane == 31) wsum[w] = v;
    __syncthreads();
    if(w == 0){
        int x = wsum[lane];
        #pragma unroll
        for(int o = 1; o < 32; o <<= 1){ int u = __shfl_up_sync(~0u, x, o); if(lane >= o) x += u; }
        wsum[lane] = x;
    }
    __syncthreads();
    int run = v - s + (w > 0 ? wsum[w-1] : 0);
    #pragma unroll
    for(int i = 0; i < 16; i++){ g_rowptr[base + i] = run; run += c[i]; }
    if(t == 1023) g_rowptr[Nn] = run;
}

__global__ void k_fill(const int* __restrict__ ei){
    int e = blockIdx.x*blockDim.x + threadIdx.x;
    if(e >= Ne) return;
    int src = ei[e];
    int pos = g_rowptr[src] + atomicAdd(&g_cursor[src], 1);
    g_edst[pos] = ei[Ne + e];
    g_eidx[pos] = e;
}

// ---------------- h = leaky(LN(x)); also emit bf16 hi/lo --------------------------
__global__ void k_ln(const float* __restrict__ sc, const float* __restrict__ bi){
    int lane = threadIdx.x & 31, w = threadIdx.x >> 5;
    int n = blockIdx.x*8 + w;
    float v0 = g_x[n*64 + lane], v1 = g_x[n*64 + 32 + lane];
    float s = v0 + v1;
    #pragma unroll
    for(int o = 16; o; o >>= 1) s += __shfl_xor_sync(0xffffffffu, s, o);
    float mu = s * 0.015625f;
    float d0 = v0 - mu, d1 = v1 - mu;
    float q = d0*d0 + d1*d1;
    #pragma unroll
    for(int o = 16; o; o >>= 1) q += __shfl_xor_sync(0xffffffffu, q, o);
    float r = rsqrtf(q * 0.015625f + 1e-5f);
    float h0 = leaky(d0*r*sc[lane]      + bi[lane]);
    float h1 = leaky(d1*r*sc[32 + lane] + bi[32 + lane]);
    g_h[n*64 + lane]      = h0;
    g_h[n*64 + 32 + lane] = h1;
    __nv_bfloat16 h0h = __float2bfloat16(h0), h1h = __float2bfloat16(h1);
    g_h_hi[n*64 + lane]      = h0h;
    g_h_hi[n*64 + 32 + lane] = h1h;
    g_h_lo[n*64 + lane]      = __float2bfloat16(h0 - __bfloat162float(h0h));
    g_h_lo[n*64 + 32 + lane] = __float2bfloat16(h1 - __bfloat162float(h1h));
}

// ---------------- mma helpers (fragment mapping VALIDATED R5/R6) -------------------
#define BPAD 72
__device__ __forceinline__ void mma_bf16(float* c, const uint32_t* a, uint32_t b0, uint32_t b1){
    asm volatile(
        "mma.sync.aligned.m16n8k16.row.col.f32.bf16.bf16.f32 "
        "{%0,%1,%2,%3}, {%4,%5,%6,%7}, {%8,%9}, {%0,%1,%2,%3};"
        : "+f"(c[0]), "+f"(c[1]), "+f"(c[2]), "+f"(c[3])
        : "r"(a[0]), "r"(a[1]), "r"(a[2]), "r"(a[3]), "r"(b0), "r"(b1));
}
__device__ __forceinline__ void ldsm_x4(uint32_t& r0, uint32_t& r1, uint32_t& r2, uint32_t& r3,
                                        uint32_t addr){
    asm volatile("ldmatrix.sync.aligned.m8n8.x4.shared.b16 {%0,%1,%2,%3}, [%4];"
        : "=r"(r0), "=r"(r1), "=r"(r2), "=r"(r3) : "r"(addr));
}

__device__ __forceinline__ void load_a_frags(const __nv_bfloat16* ph, const __nv_bfloat16* pl,
                                             int m0, int g, int tq,
                                             uint32_t ahi[4][4], uint32_t alo[4][4]){
    int r0 = (m0 + g)*64, r1 = (m0 + g + 8)*64;
    #pragma unroll
    for(int ks = 0; ks < 4; ks++){
        int c0 = ks*16 + 2*tq, c1 = c0 + 8;
        ahi[ks][0] = *(const uint32_t*)&ph[r0 + c0];
        ahi[ks][1] = *(const uint32_t*)&ph[r1 + c0];
        ahi[ks][2] = *(const uint32_t*)&ph[r0 + c1];
        ahi[ks][3] = *(const uint32_t*)&ph[r1 + c1];
        alo[ks][0] = *(const uint32_t*)&pl[r0 + c0];
        alo[ks][1] = *(const uint32_t*)&pl[r1 + c0];
        alo[ks][2] = *(const uint32_t*)&pl[r0 + c1];
        alo[ks][3] = *(const uint32_t*)&pl[r1 + c1];
    }
}

// ---------------- a = leaky(ea @ W1 + b1) via mma (unchanged, validated R6) --------
__global__ __launch_bounds__(256) void k_emlp_mma(int layer, const float* __restrict__ b1l){
    __shared__ __align__(16) __nv_bfloat16 Bh[128*BPAD];
    __shared__ __align__(16) __nv_bfloat16 Bl[128*BPAD];
    const __nv_bfloat16* w1h = g_w1t_hi + (size_t)layer*Hh*Dd;
    const __nv_bfloat16* w1l = g_w1t_lo + (size_t)layer*Hh*Dd;
    int tid = threadIdx.x, w = tid >> 5, lane = tid & 31;
    int g = lane >> 2, tq = lane & 3;
    int e0 = blockIdx.x * 128;
    int m0 = e0 + w*16;

    uint32_t ahi[4][4], alo[4][4];
    load_a_frags(g_ea_hi, g_ea_lo, m0, g, tq, ahi, alo);
    {
        const uint4* sh = (const uint4*)w1h;
        const uint4* sl = (const uint4*)w1l;
        #pragma unroll
        for(int i = 0; i < 4; i++){
            int idx = i*256 + tid;
            int f = idx >> 3, u = idx & 7;
            *(uint4*)&Bh[f*BPAD + u*8] = sh[idx];
            *(uint4*)&Bl[f*BPAD + u*8] = sl[idx];
        }
    }
    __syncthreads();

    float acc[16][4];
    #pragma unroll
    for(int j = 0; j < 16; j++)
        #pragma unroll
        for(int i = 0; i < 4; i++) acc[j][i] = 0.f;

    #pragma unroll
    for(int ks = 0; ks < 4; ks++){
        int cb0 = ks*16 + 2*tq, cb1 = cb0 + 8;
        #pragma unroll
        for(int j = 0; j < 16; j++){
            int row = (j*8 + g)*BPAD;
            uint32_t bh0 = *(const uint32_t*)&Bh[row + cb0];
            uint32_t bh1 = *(const uint32_t*)&Bh[row + cb1];
            uint32_t bl0 = *(const uint32_t*)&Bl[row + cb0];
            uint32_t bl1 = *(const uint32_t*)&Bl[row + cb1];
            mma_bf16(acc[j], ahi[ks], bh0, bh1);
            mma_bf16(acc[j], ahi[ks], bl0, bl1);
            mma_bf16(acc[j], alo[ks], bh0, bh1);
        }
    }

    float* a0 = g_a + (size_t)(m0 + g)*128;
    float* a1 = g_a + (size_t)(m0 + g + 8)*128;
    #pragma unroll
    for(int j = 0; j < 16; j++){
        int c = j*8 + 2*tq;
        float2 bb = *(const float2*)&b1l[c];
        *(float2*)&a0[c] = make_float2(leaky(acc[j][0] + bb.x), leaky(acc[j][1] + bb.y));
        *(float2*)&a1[c] = make_float2(leaky(acc[j][2] + bb.x), leaky(acc[j][3] + bb.y));
    }
}

// ---------------- Q via mma; B fragments via ldmatrix.x4 ---------------------------
__global__ __launch_bounds__(256) void k_q_mma(int layer){
    __shared__ __align__(16) __nv_bfloat16 Bh[64*BPAD];
    __shared__ __align__(16) __nv_bfloat16 Bl[64*BPAD];
    const __nv_bfloat16* w2h = g_w2t_hi + (size_t)layer*Hh*4096;
    const __nv_bfloat16* w2l = g_w2t_lo + (size_t)layer*Hh*4096;
    int tid = threadIdx.x, w = tid >> 5, lane = tid & 31;
    int g = lane >> 2, tq = lane & 3;
    int n0 = blockIdx.x * 128;
    int m0 = n0 + w*16;

    uint32_t ahi[4][4], alo[4][4];
    load_a_frags(g_h_hi, g_h_lo, m0, g, tq, ahi, alo);

    // ldmatrix lane->address base: lanes 0-15 -> Bh (matrices b0,b1),
    // lanes 16-31 -> Bl (matrices b0,b1); within each half, +0 / +8 d-offset.
    int sel = lane >> 3, rw = lane & 7;
    uint32_t lds_base;
    {
        __nv_bfloat16* arr = (sel < 2) ? Bh : Bl;
        lds_base = (uint32_t)__cvta_generic_to_shared(&arr[rw*BPAD + (sel & 1)*8]);
    }

    int kbase = blockIdx.y*8;
    uint4 pf_h0, pf_h1, pf_l0, pf_l1;
    {
        const uint4* sh = (const uint4*)(w2h + (size_t)kbase*4096);
        const uint4* sl = (const uint4*)(w2l + (size_t)kbase*4096);
        pf_h0 = sh[tid]; pf_h1 = sh[256 + tid];
        pf_l0 = sl[tid]; pf_l1 = sl[256 + tid];
    }
    int f0 = tid >> 3,         u0 = tid & 7;
    int f1 = (256 + tid) >> 3, u1 = tid & 7;

    for(int kk = 0; kk < 8; kk++){
        int k = kbase + kk;
        __syncthreads();
        *(uint4*)&Bh[f0*BPAD + u0*8] = pf_h0;
        *(uint4*)&Bh[f1*BPAD + u1*8] = pf_h1;
        *(uint4*)&Bl[f0*BPAD + u0*8] = pf_l0;
        *(uint4*)&Bl[f1*BPAD + u1*8] = pf_l1;
        if(kk < 7){
            const uint4* sh = (const uint4*)(w2h + (size_t)(k + 1)*4096);
            const uint4* sl = (const uint4*)(w2l + (size_t)(k + 1)*4096);
            pf_h0 = sh[tid]; pf_h1 = sh[256 + tid];
            pf_l0 = sl[tid]; pf_l1 = sl[256 + tid];
        }
        __syncthreads();

        float acc[8][4];
        #pragma unroll
        for(int j = 0; j < 8; j++)
            #pragma unroll
            for(int i = 0; i < 4; i++) acc[j][i] = 0.f;

        #pragma unroll
        for(int ks = 0; ks < 4; ks++){
            #pragma unroll
            for(int j = 0; j < 8; j++){
                uint32_t bh0, bh1, bl0, bl1;
                ldsm_x4(bh0, bh1, bl0, bl1,
                        lds_base + (uint32_t)((j*8*BPAD + ks*16)*2));
                mma_bf16(acc[j], ahi[ks], bh0, bh1);
                mma_bf16(acc[j], ahi[ks], bl0, bl1);
                mma_bf16(acc[j], alo[ks], bh0, bh1);
            }
        }

        __half* q0 = g_Q + ((size_t)(m0 + g)*128 + k)*64;
        __half* q1 = g_Q + ((size_t)(m0 + g + 8)*128 + k)*64;
        #pragma unroll
        for(int j = 0; j < 8; j++){
            int c = j*8 + 2*tq;
            *(__half2*)&q0[c] = __floats2half2_rn(acc[j][0], acc[j][1]);
            *(__half2*)&q1[c] = __floats2half2_rn(acc[j][2], acc[j][3]);
        }
    }
}

// ---------------- messages v3: fp16 smem Q, 8 edges/batch, f-pair lanes ------------
__global__ __launch_bounds__(256) void k_msg2(){
    __shared__ __align__(16) __half Qs[8192];   // [k][f] fp16, 16KB
    __shared__ float as[8][128];
    __shared__ float y2s[64];
    int n = blockIdx.x;
    int beg = g_rowptr[n], end = g_rowptr[n+1];
    if(beg == end) return;
    int tid = threadIdx.x;
    const uint4* qsrc = (const uint4*)(g_Q + (size_t)n*8192);
    uint4* qd = (uint4*)Qs;
    #pragma unroll
    for(int i = 0; i < 4; i++) qd[i*256 + tid] = qsrc[i*256 + tid];
    if(tid < 64) y2s[tid] = g_y2[n*64 + tid];
    __syncthreads();
    int g = tid >> 5, lane = tid & 31;
    const __half2* Q2 = (const __half2*)Qs;
    for(int base = beg; base < end; base += 8){
        #pragma unroll
        for(int i = 0; i < 4; i++){
            int idx = i*256 + tid;
            int el = idx >> 7, k = idx & 127;
            int j = base + el;
            if(j < end) as[el][k] = g_a[(size_t)g_eidx[j]*128 + k];
        }
        __syncthreads();
        int j = base + g;
        if(j < end){
            int dst = g_edst[j];
            float accx = y2s[2*lane], accy = y2s[2*lane + 1];
            #pragma unroll 8
            for(int k4 = 0; k4 < 128; k4 += 4){
                float4 av = *(const float4*)&as[g][k4];
                float2 q0 = __half22float2(Q2[(k4+0)*32 + lane]);
                float2 q1 = __half22float2(Q2[(k4+1)*32 + lane]);
                float2 q2 = __half22float2(Q2[(k4+2)*32 + lane]);
                float2 q3 = __half22float2(Q2[(k4+3)*32 + lane]);
                accx = fmaf(av.x, q0.x, accx); accy = fmaf(av.x, q0.y, accy);
                accx = fmaf(av.y, q1.x, accx); accy = fmaf(av.y, q1.y, accy);
                accx = fmaf(av.z, q2.x, accx); accy = fmaf(av.z, q2.y, accy);
                accx = fmaf(av.w, q3.x, accx); accy = fmaf(av.w, q3.y, accy);
            }
            atomicAdd(&g_num[dst*64 + 2*lane],     accx);
            atomicAdd(&g_num[dst*64 + 2*lane + 1], accy);
        }
        __syncthreads();
    }
}

// ---------------- shared 64x64 small GEMM with three epilogues ---------------------
__global__ __launch_bounds__(256) void k_nn64(const float* __restrict__ B,
                                              const float* __restrict__ bias,
                                              const float* __restrict__ cb,
                                              const int* __restrict__ batch,
                                              int mode){
    __shared__ float As[64][64];
    __shared__ float Bs[64][64];
    const float* A = (mode == 2) ? g_x : g_h;
    int tid = threadIdx.x;
    int n0 = blockIdx.x * 64;
    #pragma unroll
    for(int i = 0; i < 4; i++){
        int idx = i*256 + tid; int m = idx >> 4, d = (idx & 15) * 4;
        *(float4*)&As[m][d] = *(const float4*)&A[(size_t)(n0 + m)*64 + d];
        *(float4*)&Bs[m][d] = *(const float4*)&B[(size_t)m*64 + d];
    }
    __syncthreads();
    int tx = tid & 15, ty = tid >> 4;
    float acc[4][4];
    #pragma unroll
    for(int i = 0; i < 4; i++)
        #pragma unroll
        for(int j = 0; j < 4; j++) acc[i][j] = 0.f;

    #pragma unroll 4
    for(int d4 = 0; d4 < 64; d4 += 4){
        float4 a[4];
        #pragma unroll
        for(int i = 0; i < 4; i++) a[i] = *(float4*)&As[ty*4 + i][d4];
        #pragma unroll
        for(int dd = 0; dd < 4; dd++){
            float4 bv = *(float4*)&Bs[d4 + dd][tx*4];
            #pragma unroll
            for(int i = 0; i < 4; i++){
                float av = (dd==0)?a[i].x:(dd==1)?a[i].y:(dd==2)?a[i].z:a[i].w;
                acc[i][0] = fmaf(av, bv.x, acc[i][0]);
                acc[i][1] = fmaf(av, bv.y, acc[i][1]);
                acc[i][2] = fmaf(av, bv.z, acc[i][2]);
                acc[i][3] = fmaf(av, bv.w, acc[i][3]);
            }
        }
    }
    if(mode == 0){
        #pragma unroll
        for(int i = 0; i < 4; i++){
            float4 o; o.x = acc[i][0]; o.y = acc[i][1]; o.z = acc[i][2]; o.w = acc[i][3];
            *(float4*)&g_y2[(size_t)(n0 + ty*4 + i)*64 + tx*4] = o;
        }
    } else if(mode == 1){
        #pragma unroll
        for(int i = 0; i < 4; i++){
            int n = n0 + ty*4 + i;
            float inv = 1.f / fmaxf(g_deg[n], 1.f);
            #pragma unroll
            for(int j = 0; j < 4; j++){
                int idx = n*64 + tx*4 + j;
                float v = g_x[idx] + g_num[idx]*inv + acc[i][j] + cb[tx*4 + j];
                g_x[idx] = v;
                g_num[idx] = 0.f;
            }
        }
    } else {
        #pragma unroll
        for(int i = 0; i < 4; i++){
            int n = n0 + ty*4 + i;
            int b = batch[n];
            #pragma unroll
            for(int j = 0; j < 4; j++)
                atomicAdd(&g_pool[b*64 + tx*4 + j], acc[i][j] + bias[tx*4 + j]);
        }
    }
}

// ---------------- head -------------------------------------------------------------
__global__ void k_out(const float* __restrict__ oW, const float* __restrict__ ob,
                      float* __restrict__ out){
    __shared__ float p[64];
    int g = blockIdx.x, t = threadIdx.x;
    if(t < 64){
        float c = fmaxf(g_cnt[g], 1.f);
        p[t] = leaky(g_pool[g*64 + t] / c);
    }
    __syncthreads();
    float acc = ob[t];
    #pragma unroll 8
    for(int f = 0; f < 64; f++)
        acc = fmaf(p[f], oW[f*128 + t], acc);
    out[g*128 + t] = acc;
}

// ---------------- launch -------------------------------------------------------------
extern "C" void kernel_launch(void* const* d_in, const int* in_sizes, int n_in,
                              void* d_out, int out_size){
    const float* x    = (const float*)d_in[0];
    const int*   ei   = (const int*)  d_in[1];
    const float* ea   = (const float*)d_in[2];
    const int*   batch= (const int*)  d_in[3];
    const float* lns  = (const float*)d_in[4];
    const float* lnb  = (const float*)d_in[5];
    const float* W1   = (const float*)d_in[6];
    const float* b1   = (const float*)d_in[7];
    const float* W2   = (const float*)d_in[8];
    const float* b2   = (const float*)d_in[9];
    const float* root = (const float*)d_in[10];
    const float* cb   = (const float*)d_in[11];
    const float* dW   = (const float*)d_in[12];
    const float* db   = (const float*)d_in[13];
    const float* oW   = (const float*)d_in[14];
    const float* ob   = (const float*)d_in[15];
    float* out = (float*)d_out;

    dim3 gq(Nn/128, Hh/8);

    // Order chosen so launch index 3 (the one ncu captures) = k_q_mma(layer 0).
    k_prep<<<(Ne*Dd + 255)/256, 256>>>(W2, W1, ea);            // 0
    k_init<<<(Nn*Dd + 255)/256, 256>>>(x);                     // 1
    k_ln<<<Nn/8, 256>>>(lns, lnb);                             // 2
    k_q_mma<<<gq, 256>>>(0);                                   // 3  <- profiled
    k_degcnt<<<(Ne + 255)/256, 256>>>(ei, batch);              // 4
    k_scan<<<1, 1024>>>();                                     // 5
    k_fill<<<(Ne + 255)/256, 256>>>(ei);                       // 6
    k_emlp_mma<<<Ne/128, 256>>>(0, b1);                        // 7
    k_nn64<<<Nn/64, 256>>>(b2, nullptr, nullptr, nullptr, 0);  // 8: y2 = h@B2
    k_msg2<<<Nn, 256>>>();                                     // 9
    k_nn64<<<Nn/64, 256>>>(root, nullptr, cb, nullptr, 1);     // 10

    for(int l = 1; l < Ll; l++){
        k_ln<<<Nn/8, 256>>>(lns + l*64, lnb + l*64);
        k_emlp_mma<<<Ne/128, 256>>>(l, b1 + (size_t)l*128);
        k_nn64<<<Nn/64, 256>>>(b2 + (size_t)l*4096, nullptr, nullptr, nullptr, 0);
        k_q_mma<<<gq, 256>>>(l);
        k_msg2<<<Nn, 256>>>();
        k_nn64<<<Nn/64, 256>>>(root + (size_t)l*4096, nullptr, cb + (size_t)l*64, nullptr, 1);
    }

    k_nn64<<<Nn/64, 256>>>(dW, db, nullptr, batch, 2);  // dense + pool
    k_out<<<Gg, 128>>>(oW, ob, out);
}

// round 10
// speedup vs baseline: 1.4051x; 1.0207x over previous
#include <cuda_runtime.h>
#include <cuda_bf16.h>
#include <cuda_fp16.h>
#include <cstdint>

#define Nn 16384
#define Ne 65536
#define Dd 64
#define Hh 128
#define Ll 3
#define Gg 512
#define Oo 128

// ---------------- scratch -------------------------------------------------------
__device__ float g_x[Nn*Dd];
__device__ float g_h[Nn*Dd];
__device__ __nv_bfloat16 g_h_hi[Nn*Dd];
__device__ __nv_bfloat16 g_h_lo[Nn*Dd];
__device__ float g_y2[Nn*Dd];
__device__ float g_a[(size_t)Ne*Hh];
__device__ __half g_Q[(size_t)Nn*Hh*Dd];                 // [n][k][f], fp16, 256 MB
__device__ __nv_bfloat16 g_w2t_hi[(size_t)Ll*Hh*Dd*Dd]; // [l][k][f][d]
__device__ __nv_bfloat16 g_w2t_lo[(size_t)Ll*Hh*Dd*Dd];
__device__ __nv_bfloat16 g_w1t_hi[(size_t)Ll*Hh*Dd];    // [l][f=128][d=64]
__device__ __nv_bfloat16 g_w1t_lo[(size_t)Ll*Hh*Dd];
__device__ __nv_bfloat16 g_ea_hi[(size_t)Ne*Dd];
__device__ __nv_bfloat16 g_ea_lo[(size_t)Ne*Dd];
__device__ float g_num[Nn*Dd];
__device__ float g_deg[Nn];
__device__ float g_pool[Gg*Dd];
__device__ float g_cnt[Gg];
// CSR by src
__device__ int g_srccnt[Nn];
__device__ int g_cursor[Nn];
__device__ int g_rowptr[Nn + 1];
__device__ int g_edst[Ne];
__device__ int g_eidx[Ne];

__device__ __forceinline__ float leaky(float v){ return v > 0.f ? v : 0.01f*v; }

// ---------------- merged weight/edge prep (one launch slot) -----------------------
__global__ void k_prep(const float* __restrict__ W2, const float* __restrict__ W1,
                       const float* __restrict__ ea){
    int idx = blockIdx.x*blockDim.x + threadIdx.x;
    if(idx < Ne*Dd){
        float v = ea[idx];
        __nv_bfloat16 hi = __float2bfloat16(v);
        g_ea_hi[idx] = hi;
        g_ea_lo[idx] = __float2bfloat16(v - __bfloat162float(hi));
    }
    if(idx < Ll*Hh*Dd*Dd){
        int lk = idx >> 12;
        int d = (idx >> 6) & 63;
        int f = idx & 63;
        float v = W2[idx];
        __nv_bfloat16 hi = __float2bfloat16(v);
        __nv_bfloat16 lo = __float2bfloat16(v - __bfloat162float(hi));
        size_t o = (size_t)lk*4096 + f*64 + d;
        g_w2t_hi[o] = hi;
        g_w2t_lo[o] = lo;
    }
    if(idx < Ll*Dd*Hh){
        int l = idx >> 13;
        int d = (idx >> 7) & 63;
        int f = idx & 127;
        float v = W1[idx];
        __nv_bfloat16 hi = __float2bfloat16(v);
        __nv_bfloat16 lo = __float2bfloat16(v - __bfloat162float(hi));
        size_t o = (size_t)l*Hh*Dd + f*64 + d;
        g_w1t_hi[o] = hi;
        g_w1t_lo[o] = lo;
    }
}

// ---------------- init -----------------------------------------------------------
__global__ void k_init(const float* __restrict__ x){
    int i = blockIdx.x*blockDim.x + threadIdx.x;
    if(i < Nn*Dd){ g_x[i] = x[i]; g_num[i] = 0.f; }
    if(i < Gg*Dd) g_pool[i] = 0.f;
    if(i < Nn){ g_deg[i] = 0.f; g_srccnt[i] = 0; g_cursor[i] = 0; }
    if(i < Gg)  g_cnt[i] = 0.f;
}

__global__ void k_degcnt(const int* __restrict__ ei, const int* __restrict__ batch){
    int i = blockIdx.x*blockDim.x + threadIdx.x;
    if(i < Ne){
        atomicAdd(&g_deg[ei[Ne + i]], 1.f);
        atomicAdd(&g_srccnt[ei[i]], 1);
    }
    if(i < Nn) atomicAdd(&g_cnt[batch[i]], 1.f);
}

// single-block exclusive scan of g_srccnt -> g_rowptr
__global__ void k_scan(){
    __shared__ int wsum[32];
    int t = threadIdx.x;
    int base = t*16;
    int c[16]; int s = 0;
    #pragma unroll
    for(int i = 0; i < 16; i++){ c[i] = g_srccnt[base + i]; s += c[i]; }
    int lane = t & 31, w = t >> 5;
    int v = s;
    #pragma unroll
    for(int o = 1; o < 32; o <<= 1){ int u = __shfl_up_sync(~0u, v, o); if(lane >= o) v += u; }
    if(lane == 31) wsum[w] = v;
    __syncthreads();
    if(w == 0){
        int x = wsum[lane];
        #pragma unroll
        for(int o = 1; o < 32; o <<= 1){ int u = __shfl_up_sync(~0u, x, o); if(lane >= o) x += u; }
        wsum[lane] = x;
    }
    __syncthreads();
    int run = v - s + (w > 0 ? wsum[w-1] : 0);
    #pragma unroll
    for(int i = 0; i < 16; i++){ g_rowptr[base + i] = run; run += c[i]; }
    if(t == 1023) g_rowptr[Nn] = run;
}

__global__ void k_fill(const int* __restrict__ ei){
    int e = blockIdx.x*blockDim.x + threadIdx.x;
    if(e >= Ne) return;
    int src = ei[e];
    int pos = g_rowptr[src] + atomicAdd(&g_cursor[src], 1);
    g_edst[pos] = ei[Ne + e];
    g_eidx[pos] = e;
}

// ---------------- h = leaky(LN(x)); also emit bf16 hi/lo --------------------------
__global__ void k_ln(const float* __restrict__ sc, const float* __restrict__ bi){
    int lane = threadIdx.x & 31, w = threadIdx.x >> 5;
    int n = blockIdx.x*8 + w;
    float v0 = g_x[n*64 + lane], v1 = g_x[n*64 + 32 + lane];
    float s = v0 + v1;
    #pragma unroll
    for(int o = 16; o; o >>= 1) s += __shfl_xor_sync(0xffffffffu, s, o);
    float mu = s * 0.015625f;
    float d0 = v0 - mu, d1 = v1 - mu;
    float q = d0*d0 + d1*d1;
    #pragma unroll
    for(int o = 16; o; o >>= 1) q += __shfl_xor_sync(0xffffffffu, q, o);
    float r = rsqrtf(q * 0.015625f + 1e-5f);
    float h0 = leaky(d0*r*sc[lane]      + bi[lane]);
    float h1 = leaky(d1*r*sc[32 + lane] + bi[32 + lane]);
    g_h[n*64 + lane]      = h0;
    g_h[n*64 + 32 + lane] = h1;
    __nv_bfloat16 h0h = __float2bfloat16(h0), h1h = __float2bfloat16(h1);
    g_h_hi[n*64 + lane]      = h0h;
    g_h_hi[n*64 + 32 + lane] = h1h;
    g_h_lo[n*64 + lane]      = __float2bfloat16(h0 - __bfloat162float(h0h));
    g_h_lo[n*64 + 32 + lane] = __float2bfloat16(h1 - __bfloat162float(h1h));
}

// ---------------- mma helpers (fragment mapping VALIDATED R5/R6) -------------------
#define BPAD 72
__device__ __forceinline__ void mma_bf16(float* c, const uint32_t* a, uint32_t b0, uint32_t b1){
    asm volatile(
        "mma.sync.aligned.m16n8k16.row.col.f32.bf16.bf16.f32 "
        "{%0,%1,%2,%3}, {%4,%5,%6,%7}, {%8,%9}, {%0,%1,%2,%3};"
        : "+f"(c[0]), "+f"(c[1]), "+f"(c[2]), "+f"(c[3])
        : "r"(a[0]), "r"(a[1]), "r"(a[2]), "r"(a[3]), "r"(b0), "r"(b1));
}
__device__ __forceinline__ void ldsm_x4(uint32_t& r0, uint32_t& r1, uint32_t& r2, uint32_t& r3,
                                        uint32_t addr){
    asm volatile("ldmatrix.sync.aligned.m8n8.x4.shared.b16 {%0,%1,%2,%3}, [%4];"
        : "=r"(r0), "=r"(r1), "=r"(r2), "=r"(r3) : "r"(addr));
}

__device__ __forceinline__ void load_a_frags(const __nv_bfloat16* ph, const __nv_bfloat16* pl,
                                             int m0, int g, int tq,
                                             uint32_t ahi[4][4], uint32_t alo[4][4]){
    int r0 = (m0 + g)*64, r1 = (m0 + g + 8)*64;
    #pragma unroll
    for(int ks = 0; ks < 4; ks++){
        int c0 = ks*16 + 2*tq, c1 = c0 + 8;
        ahi[ks][0] = *(const uint32_t*)&ph[r0 + c0];
        ahi[ks][1] = *(const uint32_t*)&ph[r1 + c0];
        ahi[ks][2] = *(const uint32_t*)&ph[r0 + c1];
        ahi[ks][3] = *(const uint32_t*)&ph[r1 + c1];
        alo[ks][0] = *(const uint32_t*)&pl[r0 + c0];
        alo[ks][1] = *(const uint32_t*)&pl[r1 + c0];
        alo[ks][2] = *(const uint32_t*)&pl[r0 + c1];
        alo[ks][3] = *(const uint32_t*)&pl[r1 + c1];
    }
}

// ---------------- a = leaky(ea @ W1 + b1) via mma (unchanged, validated R6) --------
__global__ __launch_bounds__(256) void k_emlp_mma(int layer, const float* __restrict__ b1l){
    __shared__ __align__(16) __nv_bfloat16 Bh[128*BPAD];
    __shared__ __align__(16) __nv_bfloat16 Bl[128*BPAD];
    const __nv_bfloat16* w1h = g_w1t_hi + (size_t)layer*Hh*Dd;
    const __nv_bfloat16* w1l = g_w1t_lo + (size_t)layer*Hh*Dd;
    int tid = threadIdx.x, w = tid >> 5, lane = tid & 31;
    int g = lane >> 2, tq = lane & 3;
    int e0 = blockIdx.x * 128;
    int m0 = e0 + w*16;

    uint32_t ahi[4][4], alo[4][4];
    load_a_frags(g_ea_hi, g_ea_lo, m0, g, tq, ahi, alo);
    {
        const uint4* sh = (const uint4*)w1h;
        const uint4* sl = (const uint4*)w1l;
        #pragma unroll
        for(int i = 0; i < 4; i++){
            int idx = i*256 + tid;
            int f = idx >> 3, u = idx & 7;
            *(uint4*)&Bh[f*BPAD + u*8] = sh[idx];
            *(uint4*)&Bl[f*BPAD + u*8] = sl[idx];
        }
    }
    __syncthreads();

    float acc[16][4];
    #pragma unroll
    for(int j = 0; j < 16; j++)
        #pragma unroll
        for(int i = 0; i < 4; i++) acc[j][i] = 0.f;

    #pragma unroll
    for(int ks = 0; ks < 4; ks++){
        int cb0 = ks*16 + 2*tq, cb1 = cb0 + 8;
        #pragma unroll
        for(int j = 0; j < 16; j++){
            int row = (j*8 + g)*BPAD;
            uint32_t bh0 = *(const uint32_t*)&Bh[row + cb0];
            uint32_t bh1 = *(const uint32_t*)&Bh[row + cb1];
            uint32_t bl0 = *(const uint32_t*)&Bl[row + cb0];
            uint32_t bl1 = *(const uint32_t*)&Bl[row + cb1];
            mma_bf16(acc[j], ahi[ks], bh0, bh1);
            mma_bf16(acc[j], ahi[ks], bl0, bl1);
            mma_bf16(acc[j], alo[ks], bh0, bh1);
        }
    }

    float* a0 = g_a + (size_t)(m0 + g)*128;
    float* a1 = g_a + (size_t)(m0 + g + 8)*128;
    #pragma unroll
    for(int j = 0; j < 16; j++){
        int c = j*8 + 2*tq;
        float2 bb = *(const float2*)&b1l[c];
        *(float2*)&a0[c] = make_float2(leaky(acc[j][0] + bb.x), leaky(acc[j][1] + bb.y));
        *(float2*)&a1[c] = make_float2(leaky(acc[j][2] + bb.x), leaky(acc[j][3] + bb.y));
    }
}

// ---------------- Q via mma; ldmatrix B loads; smem-staged coalesced stores --------
#define DPAD 72   // D-tile row pitch in halves (144B): bank rotation 4, uint4-aligned
__global__ __launch_bounds__(256) void k_q_mma(int layer){
    __shared__ __align__(16) __nv_bfloat16 Bh[64*BPAD];
    __shared__ __align__(16) __nv_bfloat16 Bl[64*BPAD];
    __shared__ __align__(16) __half Ds[8*16*DPAD];   // per-warp 16x64 staging, 18KB
    const __nv_bfloat16* w2h = g_w2t_hi + (size_t)layer*Hh*4096;
    const __nv_bfloat16* w2l = g_w2t_lo + (size_t)layer*Hh*4096;
    int tid = threadIdx.x, w = tid >> 5, lane = tid & 31;
    int g = lane >> 2, tq = lane & 3;
    int n0 = blockIdx.x * 128;
    int m0 = n0 + w*16;

    uint32_t ahi[4][4], alo[4][4];
    load_a_frags(g_h_hi, g_h_lo, m0, g, tq, ahi, alo);

    // ldmatrix lane->address base: lanes 0-15 -> Bh, lanes 16-31 -> Bl
    int sel = lane >> 3, rw = lane & 7;
    uint32_t lds_base;
    {
        __nv_bfloat16* arr = (sel < 2) ? Bh : Bl;
        lds_base = (uint32_t)__cvta_generic_to_shared(&arr[rw*BPAD + (sel & 1)*8]);
    }

    int kbase = blockIdx.y*8;
    uint4 pf_h0, pf_h1, pf_l0, pf_l1;
    {
        const uint4* sh = (const uint4*)(w2h + (size_t)kbase*4096);
        const uint4* sl = (const uint4*)(w2l + (size_t)kbase*4096);
        pf_h0 = sh[tid]; pf_h1 = sh[256 + tid];
        pf_l0 = sl[tid]; pf_l1 = sl[256 + tid];
    }
    int f0 = tid >> 3,         u0 = tid & 7;
    int f1 = (256 + tid) >> 3, u1 = tid & 7;

    __half* ds = Ds + w*16*DPAD;

    for(int kk = 0; kk < 8; kk++){
        int k = kbase + kk;
        __syncthreads();
        *(uint4*)&Bh[f0*BPAD + u0*8] = pf_h0;
        *(uint4*)&Bh[f1*BPAD + u1*8] = pf_h1;
        *(uint4*)&Bl[f0*BPAD + u0*8] = pf_l0;
        *(uint4*)&Bl[f1*BPAD + u1*8] = pf_l1;
        if(kk < 7){
            const uint4* sh = (const uint4*)(w2h + (size_t)(k + 1)*4096);
            const uint4* sl = (const uint4*)(w2l + (size_t)(k + 1)*4096);
            pf_h0 = sh[tid]; pf_h1 = sh[256 + tid];
            pf_l0 = sl[tid]; pf_l1 = sl[256 + tid];
        }
        __syncthreads();

        float acc[8][4];
        #pragma unroll
        for(int j = 0; j < 8; j++)
            #pragma unroll
            for(int i = 0; i < 4; i++) acc[j][i] = 0.f;

        #pragma unroll
        for(int ks = 0; ks < 4; ks++){
            #pragma unroll
            for(int j = 0; j < 8; j++){
                uint32_t bh0, bh1, bl0, bl1;
                ldsm_x4(bh0, bh1, bl0, bl1,
                        lds_base + (uint32_t)((j*8*BPAD + ks*16)*2));
                mma_bf16(acc[j], ahi[ks], bh0, bh1);
                mma_bf16(acc[j], ahi[ks], bl0, bl1);
                mma_bf16(acc[j], alo[ks], bh0, bh1);
            }
        }

        // stage D tile in smem (conflict-free half2: banks 4g+4j+tq distinct)
        #pragma unroll
        for(int j = 0; j < 8; j++){
            int c = j*8 + 2*tq;
            *(__half2*)&ds[g*DPAD + c]       = __floats2half2_rn(acc[j][0], acc[j][1]);
            *(__half2*)&ds[(g + 8)*DPAD + c] = __floats2half2_rn(acc[j][2], acc[j][3]);
        }
        __syncwarp();
        // coalesced store: 8-lane groups write one 128B row segment each
        #pragma unroll
        for(int i = 0; i < 4; i++){
            int idx = i*32 + lane;
            int r = idx >> 3, u = idx & 7;
            uint4 v = *(const uint4*)&ds[r*DPAD + u*8];
            *(uint4*)(g_Q + ((size_t)(m0 + r)*128 + k)*64 + u*8) = v;
        }
        __syncwarp();
    }
}

// ---------------- messages v3: fp16 smem Q, 8 edges/batch, f-pair lanes ------------
__global__ __launch_bounds__(256) void k_msg2(){
    __shared__ __align__(16) __half Qs[8192];   // [k][f] fp16, 16KB
    __shared__ float as[8][128];
    __shared__ float y2s[64];
    int n = blockIdx.x;
    int beg = g_rowptr[n], end = g_rowptr[n+1];
    if(beg == end) return;
    int tid = threadIdx.x;
    const uint4* qsrc = (const uint4*)(g_Q + (size_t)n*8192);
    uint4* qd = (uint4*)Qs;
    #pragma unroll
    for(int i = 0; i < 4; i++) qd[i*256 + tid] = qsrc[i*256 + tid];
    if(tid < 64) y2s[tid] = g_y2[n*64 + tid];
    __syncthreads();
    int g = tid >> 5, lane = tid & 31;
    const __half2* Q2 = (const __half2*)Qs;
    for(int base = beg; base < end; base += 8){
        #pragma unroll
        for(int i = 0; i < 4; i++){
            int idx = i*256 + tid;
            int el = idx >> 7, k = idx & 127;
            int j = base + el;
            if(j < end) as[el][k] = g_a[(size_t)g_eidx[j]*128 + k];
        }
        __syncthreads();
        int j = base + g;
        if(j < end){
            int dst = g_edst[j];
            float accx = y2s[2*lane], accy = y2s[2*lane + 1];
            #pragma unroll 8
            for(int k4 = 0; k4 < 128; k4 += 4){
                float4 av = *(const float4*)&as[g][k4];
                float2 q0 = __half22float2(Q2[(k4+0)*32 + lane]);
                float2 q1 = __half22float2(Q2[(k4+1)*32 + lane]);
                float2 q2 = __half22float2(Q2[(k4+2)*32 + lane]);
                float2 q3 = __half22float2(Q2[(k4+3)*32 + lane]);
                accx = fmaf(av.x, q0.x, accx); accy = fmaf(av.x, q0.y, accy);
                accx = fmaf(av.y, q1.x, accx); accy = fmaf(av.y, q1.y, accy);
                accx = fmaf(av.z, q2.x, accx); accy = fmaf(av.z, q2.y, accy);
                accx = fmaf(av.w, q3.x, accx); accy = fmaf(av.w, q3.y, accy);
            }
            atomicAdd(&g_num[dst*64 + 2*lane],     accx);
            atomicAdd(&g_num[dst*64 + 2*lane + 1], accy);
        }
        __syncthreads();
    }
}

// ---------------- shared 64x64 small GEMM with three epilogues ---------------------
__global__ __launch_bounds__(256) void k_nn64(const float* __restrict__ B,
                                              const float* __restrict__ bias,
                                              const float* __restrict__ cb,
                                              const int* __restrict__ batch,
                                              int mode){
    __shared__ float As[64][64];
    __shared__ float Bs[64][64];
    const float* A = (mode == 2) ? g_x : g_h;
    int tid = threadIdx.x;
    int n0 = blockIdx.x * 64;
    #pragma unroll
    for(int i = 0; i < 4; i++){
        int idx = i*256 + tid; int m = idx >> 4, d = (idx & 15) * 4;
        *(float4*)&As[m][d] = *(const float4*)&A[(size_t)(n0 + m)*64 + d];
        *(float4*)&Bs[m][d] = *(const float4*)&B[(size_t)m*64 + d];
    }
    __syncthreads();
    int tx = tid & 15, ty = tid >> 4;
    float acc[4][4];
    #pragma unroll
    for(int i = 0; i < 4; i++)
        #pragma unroll
        for(int j = 0; j < 4; j++) acc[i][j] = 0.f;

    #pragma unroll 4
    for(int d4 = 0; d4 < 64; d4 += 4){
        float4 a[4];
        #pragma unroll
        for(int i = 0; i < 4; i++) a[i] = *(float4*)&As[ty*4 + i][d4];
        #pragma unroll
        for(int dd = 0; dd < 4; dd++){
            float4 bv = *(float4*)&Bs[d4 + dd][tx*4];
            #pragma unroll
            for(int i = 0; i < 4; i++){
                float av = (dd==0)?a[i].x:(dd==1)?a[i].y:(dd==2)?a[i].z:a[i].w;
                acc[i][0] = fmaf(av, bv.x, acc[i][0]);
                acc[i][1] = fmaf(av, bv.y, acc[i][1]);
                acc[i][2] = fmaf(av, bv.z, acc[i][2]);
                acc[i][3] = fmaf(av, bv.w, acc[i][3]);
            }
        }
    }
    if(mode == 0){
        #pragma unroll
        for(int i = 0; i < 4; i++){
            float4 o; o.x = acc[i][0]; o.y = acc[i][1]; o.z = acc[i][2]; o.w = acc[i][3];
            *(float4*)&g_y2[(size_t)(n0 + ty*4 + i)*64 + tx*4] = o;
        }
    } else if(mode == 1){
        #pragma unroll
        for(int i = 0; i < 4; i++){
            int n = n0 + ty*4 + i;
            float inv = 1.f / fmaxf(g_deg[n], 1.f);
            #pragma unroll
            for(int j = 0; j < 4; j++){
                int idx = n*64 + tx*4 + j;
                float v = g_x[idx] + g_num[idx]*inv + acc[i][j] + cb[tx*4 + j];
                g_x[idx] = v;
                g_num[idx] = 0.f;
            }
        }
    } else {
        #pragma unroll
        for(int i = 0; i < 4; i++){
            int n = n0 + ty*4 + i;
            int b = batch[n];
            #pragma unroll
            for(int j = 0; j < 4; j++)
                atomicAdd(&g_pool[b*64 + tx*4 + j], acc[i][j] + bias[tx*4 + j]);
        }
    }
}

// ---------------- head -------------------------------------------------------------
__global__ void k_out(const float* __restrict__ oW, const float* __restrict__ ob,
                      float* __restrict__ out){
    __shared__ float p[64];
    int g = blockIdx.x, t = threadIdx.x;
    if(t < 64){
        float c = fmaxf(g_cnt[g], 1.f);
        p[t] = leaky(g_pool[g*64 + t] / c);
    }
    __syncthreads();
    float acc = ob[t];
    #pragma unroll 8
    for(int f = 0; f < 64; f++)
        acc = fmaf(p[f], oW[f*128 + t], acc);
    out[g*128 + t] = acc;
}

// ---------------- launch -------------------------------------------------------------
extern "C" void kernel_launch(void* const* d_in, const int* in_sizes, int n_in,
                              void* d_out, int out_size){
    const float* x    = (const float*)d_in[0];
    const int*   ei   = (const int*)  d_in[1];
    const float* ea   = (const float*)d_in[2];
    const int*   batch= (const int*)  d_in[3];
    const float* lns  = (const float*)d_in[4];
    const float* lnb  = (const float*)d_in[5];
    const float* W1   = (const float*)d_in[6];
    const float* b1   = (const float*)d_in[7];
    const float* W2   = (const float*)d_in[8];
    const float* b2   = (const float*)d_in[9];
    const float* root = (const float*)d_in[10];
    const float* cb   = (const float*)d_in[11];
    const float* dW   = (const float*)d_in[12];
    const float* db   = (const float*)d_in[13];
    const float* oW   = (const float*)d_in[14];
    const float* ob   = (const float*)d_in[15];
    float* out = (float*)d_out;

    dim3 gq(Nn/128, Hh/8);

    // Order chosen so launch index 3 (the one ncu captures) = k_q_mma(layer 0).
    k_prep<<<(Ne*Dd + 255)/256, 256>>>(W2, W1, ea);            // 0
    k_init<<<(Nn*Dd + 255)/256, 256>>>(x);                     // 1
    k_ln<<<Nn/8, 256>>>(lns, lnb);                             // 2
    k_q_mma<<<gq, 256>>>(0);                                   // 3  <- profiled
    k_degcnt<<<(Ne + 255)/256, 256>>>(ei, batch);              // 4
    k_scan<<<1, 1024>>>();                                     // 5
    k_fill<<<(Ne + 255)/256, 256>>>(ei);                       // 6
    k_emlp_mma<<<Ne/128, 256>>>(0, b1);                        // 7
    k_nn64<<<Nn/64, 256>>>(b2, nullptr, nullptr, nullptr, 0);  // 8: y2 = h@B2
    k_msg2<<<Nn, 256>>>();                                     // 9
    k_nn64<<<Nn/64, 256>>>(root, nullptr, cb, nullptr, 1);     // 10

    for(int l = 1; l < Ll; l++){
        k_ln<<<Nn/8, 256>>>(lns + l*64, lnb + l*64);
        k_emlp_mma<<<Ne/128, 256>>>(l, b1 + (size_t)l*128);
        k_nn64<<<Nn/64, 256>>>(b2 + (size_t)l*4096, nullptr, nullptr, nullptr, 0);
        k_q_mma<<<gq, 256>>>(l);
        k_msg2<<<Nn, 256>>>();
        k_nn64<<<Nn/64, 256>>>(root + (size_t)l*4096, nullptr, cb + (size_t)l*64, nullptr, 1);
    }

    k_nn64<<<Nn/64, 256>>>(dW, db, nullptr, batch, 2);  // dense + pool
    k_out<<<Gg, 128>>>(oW, ob, out);
}

// round 11
// speedup vs baseline: 1.4396x; 1.0246x over previous
#include <cuda_runtime.h>
#include <cuda_bf16.h>
#include <cuda_fp16.h>
#include <cstdint>

#define Nn 16384
#define Ne 65536
#define Dd 64
#define Hh 128
#define Ll 3
#define Gg 512
#define Oo 128

// ---------------- scratch -------------------------------------------------------
__device__ float g_x[Nn*Dd];
__device__ float g_h[Nn*Dd];
__device__ __nv_bfloat16 g_h_hi[Nn*Dd];
__device__ __nv_bfloat16 g_h_lo[Nn*Dd];
__device__ float g_y2[Nn*Dd];
__device__ float g_a[(size_t)Ne*Hh];
__device__ __half g_Q[(size_t)Nn*Hh*Dd];                 // [n][k][f], fp16, 256 MB
__device__ __nv_bfloat16 g_w2t_hi[(size_t)Ll*Hh*Dd*Dd]; // [l][k][f][d]
__device__ __nv_bfloat16 g_w2t_lo[(size_t)Ll*Hh*Dd*Dd];
__device__ __nv_bfloat16 g_w1t_hi[(size_t)Ll*Hh*Dd];    // [l][f=128][d=64]
__device__ __nv_bfloat16 g_w1t_lo[(size_t)Ll*Hh*Dd];
__device__ __nv_bfloat16 g_ea_hi[(size_t)Ne*Dd];
__device__ __nv_bfloat16 g_ea_lo[(size_t)Ne*Dd];
__device__ float g_num[Nn*Dd];
__device__ float g_deg[Nn];
__device__ float g_pool[Gg*Dd];
__device__ float g_cnt[Gg];
// CSR by src
__device__ int g_srccnt[Nn];
__device__ int g_cursor[Nn];
__device__ int g_rowptr[Nn + 1];
__device__ int g_edst[Ne];
__device__ int g_eidx[Ne];

__device__ __forceinline__ float leaky(float v){ return v > 0.f ? v : 0.01f*v; }

// ---------------- merged weight/edge prep (one launch slot) -----------------------
__global__ void k_prep(const float* __restrict__ W2, const float* __restrict__ W1,
                       const float* __restrict__ ea){
    int idx = blockIdx.x*blockDim.x + threadIdx.x;
    if(idx < Ne*Dd){
        float v = ea[idx];
        __nv_bfloat16 hi = __float2bfloat16(v);
        g_ea_hi[idx] = hi;
        g_ea_lo[idx] = __float2bfloat16(v - __bfloat162float(hi));
    }
    if(idx < Ll*Hh*Dd*Dd){
        int lk = idx >> 12;
        int d = (idx >> 6) & 63;
        int f = idx & 63;
        float v = W2[idx];
        __nv_bfloat16 hi = __float2bfloat16(v);
        __nv_bfloat16 lo = __float2bfloat16(v - __bfloat162float(hi));
        size_t o = (size_t)lk*4096 + f*64 + d;
        g_w2t_hi[o] = hi;
        g_w2t_lo[o] = lo;
    }
    if(idx < Ll*Dd*Hh){
        int l = idx >> 13;
        int d = (idx >> 7) & 63;
        int f = idx & 127;
        float v = W1[idx];
        __nv_bfloat16 hi = __float2bfloat16(v);
        __nv_bfloat16 lo = __float2bfloat16(v - __bfloat162float(hi));
        size_t o = (size_t)l*Hh*Dd + f*64 + d;
        g_w1t_hi[o] = hi;
        g_w1t_lo[o] = lo;
    }
}

// ---------------- init -----------------------------------------------------------
__global__ void k_init(const float* __restrict__ x){
    int i = blockIdx.x*blockDim.x + threadIdx.x;
    if(i < Nn*Dd){ g_x[i] = x[i]; g_num[i] = 0.f; }
    if(i < Gg*Dd) g_pool[i] = 0.f;
    if(i < Nn){ g_deg[i] = 0.f; g_srccnt[i] = 0; g_cursor[i] = 0; }
    if(i < Gg)  g_cnt[i] = 0.f;
}

__global__ void k_degcnt(const int* __restrict__ ei, const int* __restrict__ batch){
    int i = blockIdx.x*blockDim.x + threadIdx.x;
    if(i < Ne){
        atomicAdd(&g_deg[ei[Ne + i]], 1.f);
        atomicAdd(&g_srccnt[ei[i]], 1);
    }
    if(i < Nn) atomicAdd(&g_cnt[batch[i]], 1.f);
}

// single-block exclusive scan of g_srccnt -> g_rowptr
__global__ void k_scan(){
    __shared__ int wsum[32];
    int t = threadIdx.x;
    int base = t*16;
    int c[16]; int s = 0;
    #pragma unroll
    for(int i = 0; i < 16; i++){ c[i] = g_srccnt[base + i]; s += c[i]; }
    int lane = t & 31, w = t >> 5;
    int v = s;
    #pragma unroll
    for(int o = 1; o < 32; o <<= 1){ int u = __shfl_up_sync(~0u, v, o); if(lane >= o) v += u; }
    if(lane == 31) wsum[w] = v;
    __syncthreads();
    if(w == 0){
        int x = wsum[lane];
        #pragma unroll
        for(int o = 1; o < 32; o <<= 1){ int u = __shfl_up_sync(~0u, x, o); if(lane >= o) x += u; }
        wsum[lane] = x;
    }
    __syncthreads();
    int run = v - s + (w > 0 ? wsum[w-1] : 0);
    #pragma unroll
    for(int i = 0; i < 16; i++){ g_rowptr[base + i] = run; run += c[i]; }
    if(t == 1023) g_rowptr[Nn] = run;
}

__global__ void k_fill(const int* __restrict__ ei){
    int e = blockIdx.x*blockDim.x + threadIdx.x;
    if(e >= Ne) return;
    int src = ei[e];
    int pos = g_rowptr[src] + atomicAdd(&g_cursor[src], 1);
    g_edst[pos] = ei[Ne + e];
    g_eidx[pos] = e;
}

// ---------------- h = leaky(LN(x)); also emit bf16 hi/lo --------------------------
__global__ void k_ln(const float* __restrict__ sc, const float* __restrict__ bi){
    int lane = threadIdx.x & 31, w = threadIdx.x >> 5;
    int n = blockIdx.x*8 + w;
    float v0 = g_x[n*64 + lane], v1 = g_x[n*64 + 32 + lane];
    float s = v0 + v1;
    #pragma unroll
    for(int o = 16; o; o >>= 1) s += __shfl_xor_sync(0xffffffffu, s, o);
    float mu = s * 0.015625f;
    float d0 = v0 - mu, d1 = v1 - mu;
    float q = d0*d0 + d1*d1;
    #pragma unroll
    for(int o = 16; o; o >>= 1) q += __shfl_xor_sync(0xffffffffu, q, o);
    float r = rsqrtf(q * 0.015625f + 1e-5f);
    float h0 = leaky(d0*r*sc[lane]      + bi[lane]);
    float h1 = leaky(d1*r*sc[32 + lane] + bi[32 + lane]);
    g_h[n*64 + lane]      = h0;
    g_h[n*64 + 32 + lane] = h1;
    __nv_bfloat16 h0h = __float2bfloat16(h0), h1h = __float2bfloat16(h1);
    g_h_hi[n*64 + lane]      = h0h;
    g_h_hi[n*64 + 32 + lane] = h1h;
    g_h_lo[n*64 + lane]      = __float2bfloat16(h0 - __bfloat162float(h0h));
    g_h_lo[n*64 + 32 + lane] = __float2bfloat16(h1 - __bfloat162float(h1h));
}

// ---------------- mma helpers (fragment mapping VALIDATED R5/R6) -------------------
#define BPAD 72
__device__ __forceinline__ void mma_bf16(float* c, const uint32_t* a, uint32_t b0, uint32_t b1){
    asm volatile(
        "mma.sync.aligned.m16n8k16.row.col.f32.bf16.bf16.f32 "
        "{%0,%1,%2,%3}, {%4,%5,%6,%7}, {%8,%9}, {%0,%1,%2,%3};"
        : "+f"(c[0]), "+f"(c[1]), "+f"(c[2]), "+f"(c[3])
        : "r"(a[0]), "r"(a[1]), "r"(a[2]), "r"(a[3]), "r"(b0), "r"(b1));
}
__device__ __forceinline__ void ldsm_x4(uint32_t& r0, uint32_t& r1, uint32_t& r2, uint32_t& r3,
                                        uint32_t addr){
    asm volatile("ldmatrix.sync.aligned.m8n8.x4.shared.b16 {%0,%1,%2,%3}, [%4];"
        : "=r"(r0), "=r"(r1), "=r"(r2), "=r"(r3) : "r"(addr));
}

__device__ __forceinline__ void load_a_frags(const __nv_bfloat16* ph, const __nv_bfloat16* pl,
                                             int m0, int g, int tq,
                                             uint32_t ahi[4][4], uint32_t alo[4][4]){
    int r0 = (m0 + g)*64, r1 = (m0 + g + 8)*64;
    #pragma unroll
    for(int ks = 0; ks < 4; ks++){
        int c0 = ks*16 + 2*tq, c1 = c0 + 8;
        ahi[ks][0] = *(const uint32_t*)&ph[r0 + c0];
        ahi[ks][1] = *(const uint32_t*)&ph[r1 + c0];
        ahi[ks][2] = *(const uint32_t*)&ph[r0 + c1];
        ahi[ks][3] = *(const uint32_t*)&ph[r1 + c1];
        alo[ks][0] = *(const uint32_t*)&pl[r0 + c0];
        alo[ks][1] = *(const uint32_t*)&pl[r1 + c0];
        alo[ks][2] = *(const uint32_t*)&pl[r0 + c1];
        alo[ks][3] = *(const uint32_t*)&pl[r1 + c1];
    }
}

// ---------------- a = leaky(ea @ W1 + b1) via mma (unchanged, validated R6) --------
__global__ __launch_bounds__(256) void k_emlp_mma(int layer, const float* __restrict__ b1l){
    __shared__ __align__(16) __nv_bfloat16 Bh[128*BPAD];
    __shared__ __align__(16) __nv_bfloat16 Bl[128*BPAD];
    const __nv_bfloat16* w1h = g_w1t_hi + (size_t)layer*Hh*Dd;
    const __nv_bfloat16* w1l = g_w1t_lo + (size_t)layer*Hh*Dd;
    int tid = threadIdx.x, w = tid >> 5, lane = tid & 31;
    int g = lane >> 2, tq = lane & 3;
    int e0 = blockIdx.x * 128;
    int m0 = e0 + w*16;

    uint32_t ahi[4][4], alo[4][4];
    load_a_frags(g_ea_hi, g_ea_lo, m0, g, tq, ahi, alo);
    {
        const uint4* sh = (const uint4*)w1h;
        const uint4* sl = (const uint4*)w1l;
        #pragma unroll
        for(int i = 0; i < 4; i++){
            int idx = i*256 + tid;
            int f = idx >> 3, u = idx & 7;
            *(uint4*)&Bh[f*BPAD + u*8] = sh[idx];
            *(uint4*)&Bl[f*BPAD + u*8] = sl[idx];
        }
    }
    __syncthreads();

    float acc[16][4];
    #pragma unroll
    for(int j = 0; j < 16; j++)
        #pragma unroll
        for(int i = 0; i < 4; i++) acc[j][i] = 0.f;

    #pragma unroll
    for(int ks = 0; ks < 4; ks++){
        int cb0 = ks*16 + 2*tq, cb1 = cb0 + 8;
        #pragma unroll
        for(int j = 0; j < 16; j++){
            int row = (j*8 + g)*BPAD;
            uint32_t bh0 = *(const uint32_t*)&Bh[row + cb0];
            uint32_t bh1 = *(const uint32_t*)&Bh[row + cb1];
            uint32_t bl0 = *(const uint32_t*)&Bl[row + cb0];
            uint32_t bl1 = *(const uint32_t*)&Bl[row + cb1];
            mma_bf16(acc[j], ahi[ks], bh0, bh1);
            mma_bf16(acc[j], ahi[ks], bl0, bl1);
            mma_bf16(acc[j], alo[ks], bh0, bh1);
        }
    }

    float* a0 = g_a + (size_t)(m0 + g)*128;
    float* a1 = g_a + (size_t)(m0 + g + 8)*128;
    #pragma unroll
    for(int j = 0; j < 16; j++){
        int c = j*8 + 2*tq;
        float2 bb = *(const float2*)&b1l[c];
        *(float2*)&a0[c] = make_float2(leaky(acc[j][0] + bb.x), leaky(acc[j][1] + bb.y));
        *(float2*)&a1[c] = make_float2(leaky(acc[j][2] + bb.x), leaky(acc[j][3] + bb.y));
    }
}

// ---------------- Q via mma; ldmatrix; D staging UNIONED with B buffers ------------
// B (Bh+Bl, 18432B) and Ds (8 warps x 16 x DPAD halves, 18432B) are never live
// simultaneously: B consumed by ldsm before staging; staging done before next
// iteration's B store (top-of-loop barrier). Union halves smem -> 2 CTAs/SM.
#define DPAD 72
__global__ __launch_bounds__(256, 2) void k_q_mma(int layer){
    __shared__ __align__(16) char smem_raw[18432];
    __nv_bfloat16* Bh = (__nv_bfloat16*)smem_raw;              // 64*BPAD*2 = 9216 B
    __nv_bfloat16* Bl = (__nv_bfloat16*)(smem_raw + 9216);
    __half* Ds = (__half*)smem_raw;                             // 8*16*DPAD*2 = 18432 B
    const __nv_bfloat16* w2h = g_w2t_hi + (size_t)layer*Hh*4096;
    const __nv_bfloat16* w2l = g_w2t_lo + (size_t)layer*Hh*4096;
    int tid = threadIdx.x, w = tid >> 5, lane = tid & 31;
    int g = lane >> 2, tq = lane & 3;
    int n0 = blockIdx.x * 128;
    int m0 = n0 + w*16;

    uint32_t ahi[4][4], alo[4][4];
    load_a_frags(g_h_hi, g_h_lo, m0, g, tq, ahi, alo);

    // ldmatrix lane->address base: lanes 0-15 -> Bh, lanes 16-31 -> Bl
    int sel = lane >> 3, rw = lane & 7;
    uint32_t lds_base;
    {
        __nv_bfloat16* arr = (sel < 2) ? Bh : Bl;
        lds_base = (uint32_t)__cvta_generic_to_shared(&arr[rw*BPAD + (sel & 1)*8]);
    }

    int kbase = blockIdx.y*8;
    uint4 pf_h0, pf_h1, pf_l0, pf_l1;
    {
        const uint4* sh = (const uint4*)(w2h + (size_t)kbase*4096);
        const uint4* sl = (const uint4*)(w2l + (size_t)kbase*4096);
        pf_h0 = sh[tid]; pf_h1 = sh[256 + tid];
        pf_l0 = sl[tid]; pf_l1 = sl[256 + tid];
    }
    int f0 = tid >> 3,         u0 = tid & 7;
    int f1 = (256 + tid) >> 3, u1 = tid & 7;

    __half* ds = Ds + w*16*DPAD;

    for(int kk = 0; kk < 8; kk++){
        int k = kbase + kk;
        __syncthreads();                       // prev D staging complete
        *(uint4*)&Bh[f0*BPAD + u0*8] = pf_h0;
        *(uint4*)&Bh[f1*BPAD + u1*8] = pf_h1;
        *(uint4*)&Bl[f0*BPAD + u0*8] = pf_l0;
        *(uint4*)&Bl[f1*BPAD + u1*8] = pf_l1;
        if(kk < 7){
            const uint4* sh = (const uint4*)(w2h + (size_t)(k + 1)*4096);
            const uint4* sl = (const uint4*)(w2l + (size_t)(k + 1)*4096);
            pf_h0 = sh[tid]; pf_h1 = sh[256 + tid];
            pf_l0 = sl[tid]; pf_l1 = sl[256 + tid];
        }
        __syncthreads();                       // B visible to all warps

        float acc[8][4];
        #pragma unroll
        for(int j = 0; j < 8; j++)
            #pragma unroll
            for(int i = 0; i < 4; i++) acc[j][i] = 0.f;

        #pragma unroll
        for(int ks = 0; ks < 4; ks++){
            #pragma unroll
            for(int j = 0; j < 8; j++){
                uint32_t bh0, bh1, bl0, bl1;
                ldsm_x4(bh0, bh1, bl0, bl1,
                        lds_base + (uint32_t)((j*8*BPAD + ks*16)*2));
                mma_bf16(acc[j], ahi[ks], bh0, bh1);
                mma_bf16(acc[j], ahi[ks], bl0, bl1);
                mma_bf16(acc[j], alo[ks], bh0, bh1);
            }
        }
        __syncthreads();                       // all warps done reading B

        // stage D tile into the unioned buffer, then coalesced store
        #pragma unroll
        for(int j = 0; j < 8; j++){
            int c = j*8 + 2*tq;
            *(__half2*)&ds[g*DPAD + c]       = __floats2half2_rn(acc[j][0], acc[j][1]);
            *(__half2*)&ds[(g + 8)*DPAD + c] = __floats2half2_rn(acc[j][2], acc[j][3]);
        }
        __syncwarp();
        #pragma unroll
        for(int i = 0; i < 4; i++){
            int idx = i*32 + lane;
            int r = idx >> 3, u = idx & 7;
            uint4 v = *(const uint4*)&ds[r*DPAD + u*8];
            *(uint4*)(g_Q + ((size_t)(m0 + r)*128 + k)*64 + u*8) = v;
        }
    }
}

// ---------------- messages v3: fp16 smem Q, 8 edges/batch, f-pair lanes ------------
__global__ __launch_bounds__(256) void k_msg2(){
    __shared__ __align__(16) __half Qs[8192];   // [k][f] fp16, 16KB
    __shared__ float as[8][128];
    __shared__ float y2s[64];
    int n = blockIdx.x;
    int beg = g_rowptr[n], end = g_rowptr[n+1];
    if(beg == end) return;
    int tid = threadIdx.x;
    const uint4* qsrc = (const uint4*)(g_Q + (size_t)n*8192);
    uint4* qd = (uint4*)Qs;
    #pragma unroll
    for(int i = 0; i < 4; i++) qd[i*256 + tid] = qsrc[i*256 + tid];
    if(tid < 64) y2s[tid] = g_y2[n*64 + tid];
    __syncthreads();
    int g = tid >> 5, lane = tid & 31;
    const __half2* Q2 = (const __half2*)Qs;
    for(int base = beg; base < end; base += 8){
        #pragma unroll
        for(int i = 0; i < 4; i++){
            int idx = i*256 + tid;
            int el = idx >> 7, k = idx & 127;
            int j = base + el;
            if(j < end) as[el][k] = g_a[(size_t)g_eidx[j]*128 + k];
        }
        __syncthreads();
        int j = base + g;
        if(j < end){
            int dst = g_edst[j];
            float accx = y2s[2*lane], accy = y2s[2*lane + 1];
            #pragma unroll 8
            for(int k4 = 0; k4 < 128; k4 += 4){
                float4 av = *(const float4*)&as[g][k4];
                float2 q0 = __half22float2(Q2[(k4+0)*32 + lane]);
                float2 q1 = __half22float2(Q2[(k4+1)*32 + lane]);
                float2 q2 = __half22float2(Q2[(k4+2)*32 + lane]);
                float2 q3 = __half22float2(Q2[(k4+3)*32 + lane]);
                accx = fmaf(av.x, q0.x, accx); accy = fmaf(av.x, q0.y, accy);
                accx = fmaf(av.y, q1.x, accx); accy = fmaf(av.y, q1.y, accy);
                accx = fmaf(av.z, q2.x, accx); accy = fmaf(av.z, q2.y, accy);
                accx = fmaf(av.w, q3.x, accx); accy = fmaf(av.w, q3.y, accy);
            }
            atomicAdd(&g_num[dst*64 + 2*lane],     accx);
            atomicAdd(&g_num[dst*64 + 2*lane + 1], accy);
        }
        __syncthreads();
    }
}

// ---------------- shared 64x64 small GEMM with three epilogues ---------------------
__global__ __launch_bounds__(256) void k_nn64(const float* __restrict__ B,
                                              const float* __restrict__ bias,
                                              const float* __restrict__ cb,
                                              const int* __restrict__ batch,
                                              int mode){
    __shared__ float As[64][64];
    __shared__ float Bs[64][64];
    const float* A = (mode == 2) ? g_x : g_h;
    int tid = threadIdx.x;
    int n0 = blockIdx.x * 64;
    #pragma unroll
    for(int i = 0; i < 4; i++){
        int idx = i*256 + tid; int m = idx >> 4, d = (idx & 15) * 4;
        *(float4*)&As[m][d] = *(const float4*)&A[(size_t)(n0 + m)*64 + d];
        *(float4*)&Bs[m][d] = *(const float4*)&B[(size_t)m*64 + d];
    }
    __syncthreads();
    int tx = tid & 15, ty = tid >> 4;
    float acc[4][4];
    #pragma unroll
    for(int i = 0; i < 4; i++)
        #pragma unroll
        for(int j = 0; j < 4; j++) acc[i][j] = 0.f;

    #pragma unroll 4
    for(int d4 = 0; d4 < 64; d4 += 4){
        float4 a[4];
        #pragma unroll
        for(int i = 0; i < 4; i++) a[i] = *(float4*)&As[ty*4 + i][d4];
        #pragma unroll
        for(int dd = 0; dd < 4; dd++){
            float4 bv = *(float4*)&Bs[d4 + dd][tx*4];
            #pragma unroll
            for(int i = 0; i < 4; i++){
                float av = (dd==0)?a[i].x:(dd==1)?a[i].y:(dd==2)?a[i].z:a[i].w;
                acc[i][0] = fmaf(av, bv.x, acc[i][0]);
                acc[i][1] = fmaf(av, bv.y, acc[i][1]);
                acc[i][2] = fmaf(av, bv.z, acc[i][2]);
                acc[i][3] = fmaf(av, bv.w, acc[i][3]);
            }
        }
    }
    if(mode == 0){
        #pragma unroll
        for(int i = 0; i < 4; i++){
            float4 o; o.x = acc[i][0]; o.y = acc[i][1]; o.z = acc[i][2]; o.w = acc[i][3];
            *(float4*)&g_y2[(size_t)(n0 + ty*4 + i)*64 + tx*4] = o;
        }
    } else if(mode == 1){
        #pragma unroll
        for(int i = 0; i < 4; i++){
            int n = n0 + ty*4 + i;
            float inv = 1.f / fmaxf(g_deg[n], 1.f);
            #pragma unroll
            for(int j = 0; j < 4; j++){
                int idx = n*64 + tx*4 + j;
                float v = g_x[idx] + g_num[idx]*inv + acc[i][j] + cb[tx*4 + j];
                g_x[idx] = v;
                g_num[idx] = 0.f;
            }
        }
    } else {
        #pragma unroll
        for(int i = 0; i < 4; i++){
            int n = n0 + ty*4 + i;
            int b = batch[n];
            #pragma unroll
            for(int j = 0; j < 4; j++)
                atomicAdd(&g_pool[b*64 + tx*4 + j], acc[i][j] + bias[tx*4 + j]);
        }
    }
}

// ---------------- head -------------------------------------------------------------
__global__ void k_out(const float* __restrict__ oW, const float* __restrict__ ob,
                      float* __restrict__ out){
    __shared__ float p[64];
    int g = blockIdx.x, t = threadIdx.x;
    if(t < 64){
        float c = fmaxf(g_cnt[g], 1.f);
        p[t] = leaky(g_pool[g*64 + t] / c);
    }
    __syncthreads();
    float acc = ob[t];
    #pragma unroll 8
    for(int f = 0; f < 64; f++)
        acc = fmaf(p[f], oW[f*128 + t], acc);
    out[g*128 + t] = acc;
}

// ---------------- launch -------------------------------------------------------------
extern "C" void kernel_launch(void* const* d_in, const int* in_sizes, int n_in,
                              void* d_out, int out_size){
    const float* x    = (const float*)d_in[0];
    const int*   ei   = (const int*)  d_in[1];
    const float* ea   = (const float*)d_in[2];
    const int*   batch= (const int*)  d_in[3];
    const float* lns  = (const float*)d_in[4];
    const float* lnb  = (const float*)d_in[5];
    const float* W1   = (const float*)d_in[6];
    const float* b1   = (const float*)d_in[7];
    const float* W2   = (const float*)d_in[8];
    const float* b2   = (const float*)d_in[9];
    const float* root = (const float*)d_in[10];
    const float* cb   = (const float*)d_in[11];
    const float* dW   = (const float*)d_in[12];
    const float* db   = (const float*)d_in[13];
    const float* oW   = (const float*)d_in[14];
    const float* ob   = (const float*)d_in[15];
    float* out = (float*)d_out;

    dim3 gq(Nn/128, Hh/8);

    // Order chosen so launch index 3 (the one ncu captures) = k_q_mma(layer 0).
    k_prep<<<(Ne*Dd + 255)/256, 256>>>(W2, W1, ea);            // 0
    k_init<<<(Nn*Dd + 255)/256, 256>>>(x);                     // 1
    k_ln<<<Nn/8, 256>>>(lns, lnb);                             // 2
    k_q_mma<<<gq, 256>>>(0);                                   // 3  <- profiled
    k_degcnt<<<(Ne + 255)/256, 256>>>(ei, batch);              // 4
    k_scan<<<1, 1024>>>();                                     // 5
    k_fill<<<(Ne + 255)/256, 256>>>(ei);                       // 6
    k_emlp_mma<<<Ne/128, 256>>>(0, b1);                        // 7
    k_nn64<<<Nn/64, 256>>>(b2, nullptr, nullptr, nullptr, 0);  // 8: y2 = h@B2
    k_msg2<<<Nn, 256>>>();                                     // 9
    k_nn64<<<Nn/64, 256>>>(root, nullptr, cb, nullptr, 1);     // 10

    for(int l = 1; l < Ll; l++){
        k_ln<<<Nn/8, 256>>>(lns + l*64, lnb + l*64);
        k_emlp_mma<<<Ne/128, 256>>>(l, b1 + (size_t)l*128);
        k_nn64<<<Nn/64, 256>>>(b2 + (size_t)l*4096, nullptr, nullptr, nullptr, 0);
        k_q_mma<<<gq, 256>>>(l);
        k_msg2<<<Nn, 256>>>();
        k_nn64<<<Nn/64, 256>>>(root + (size_t)l*4096, nullptr, cb + (size_t)l*64, nullptr, 1);
    }

    k_nn64<<<Nn/64, 256>>>(dW, db, nullptr, batch, 2);  // dense + pool
    k_out<<<Gg, 128>>>(oW, ob, out);
}

// round 12
// speedup vs baseline: 1.7076x; 1.1862x over previous
#include <cuda_runtime.h>
#include <cuda_bf16.h>
#include <cuda_fp16.h>
#include <cstdint>

#define Nn 16384
#define Ne 65536
#define Dd 64
#define Hh 128
#define Ll 3
#define Gg 512
#define Oo 128

// ---------------- scratch -------------------------------------------------------
__device__ float g_x[Nn*Dd];
__device__ float g_h[Nn*Dd];
__device__ __half g_h16[Nn*Dd];                          // fp16 h for Q-GEMM A
__device__ float g_y2[Nn*Dd];
__device__ float g_a[(size_t)Ne*Hh];
__device__ __half g_Q[(size_t)Nn*Hh*Dd];                 // [n][k][f], fp16, 256 MB
__device__ __half g_w2t_hi[(size_t)Ll*Hh*Dd*Dd];        // [l][k][f][d] fp16 hi
__device__ __half g_w2t_lo[(size_t)Ll*Hh*Dd*Dd];        // fp16 lo
__device__ __nv_bfloat16 g_w1t_hi[(size_t)Ll*Hh*Dd];    // [l][f=128][d=64]
__device__ __nv_bfloat16 g_w1t_lo[(size_t)Ll*Hh*Dd];
__device__ __nv_bfloat16 g_ea_hi[(size_t)Ne*Dd];
__device__ __nv_bfloat16 g_ea_lo[(size_t)Ne*Dd];
__device__ float g_num[Nn*Dd];
__device__ float g_deg[Nn];
__device__ float g_pool[Gg*Dd];
__device__ float g_cnt[Gg];
// CSR by src
__device__ int g_srccnt[Nn];
__device__ int g_cursor[Nn];
__device__ int g_rowptr[Nn + 1];
__device__ int g_edst[Ne];
__device__ int g_eidx[Ne];

__device__ __forceinline__ float leaky(float v){ return v > 0.f ? v : 0.01f*v; }

// ---------------- merged weight/edge prep (one launch slot) -----------------------
__global__ void k_prep(const float* __restrict__ W2, const float* __restrict__ W1,
                       const float* __restrict__ ea){
    int idx = blockIdx.x*blockDim.x + threadIdx.x;
    if(idx < Ne*Dd){
        float v = ea[idx];
        __nv_bfloat16 hi = __float2bfloat16(v);
        g_ea_hi[idx] = hi;
        g_ea_lo[idx] = __float2bfloat16(v - __bfloat162float(hi));
    }
    if(idx < Ll*Hh*Dd*Dd){
        int lk = idx >> 12;
        int d = (idx >> 6) & 63;
        int f = idx & 63;
        float v = W2[idx];
        __half hi = __float2half(v);
        __half lo = __float2half(v - __half2float(hi));
        size_t o = (size_t)lk*4096 + f*64 + d;
        g_w2t_hi[o] = hi;
        g_w2t_lo[o] = lo;
    }
    if(idx < Ll*Dd*Hh){
        int l = idx >> 13;
        int d = (idx >> 7) & 63;
        int f = idx & 127;
        float v = W1[idx];
        __nv_bfloat16 hi = __float2bfloat16(v);
        __nv_bfloat16 lo = __float2bfloat16(v - __bfloat162float(hi));
        size_t o = (size_t)l*Hh*Dd + f*64 + d;
        g_w1t_hi[o] = hi;
        g_w1t_lo[o] = lo;
    }
}

// ---------------- init -----------------------------------------------------------
__global__ void k_init(const float* __restrict__ x){
    int i = blockIdx.x*blockDim.x + threadIdx.x;
    if(i < Nn*Dd){ g_x[i] = x[i]; g_num[i] = 0.f; }
    if(i < Gg*Dd) g_pool[i] = 0.f;
    if(i < Nn){ g_deg[i] = 0.f; g_srccnt[i] = 0; g_cursor[i] = 0; }
    if(i < Gg)  g_cnt[i] = 0.f;
}

__global__ void k_degcnt(const int* __restrict__ ei, const int* __restrict__ batch){
    int i = blockIdx.x*blockDim.x + threadIdx.x;
    if(i < Ne){
        atomicAdd(&g_deg[ei[Ne + i]], 1.f);
        atomicAdd(&g_srccnt[ei[i]], 1);
    }
    if(i < Nn) atomicAdd(&g_cnt[batch[i]], 1.f);
}

// single-block exclusive scan of g_srccnt -> g_rowptr
__global__ void k_scan(){
    __shared__ int wsum[32];
    int t = threadIdx.x;
    int base = t*16;
    int c[16]; int s = 0;
    #pragma unroll
    for(int i = 0; i < 16; i++){ c[i] = g_srccnt[base + i]; s += c[i]; }
    int lane = t & 31, w = t >> 5;
    int v = s;
    #pragma unroll
    for(int o = 1; o < 32; o <<= 1){ int u = __shfl_up_sync(~0u, v, o); if(lane >= o) v += u; }
    if(lane == 31) wsum[w] = v;
    __syncthreads();
    if(w == 0){
        int x = wsum[lane];
        #pragma unroll
        for(int o = 1; o < 32; o <<= 1){ int u = __shfl_up_sync(~0u, x, o); if(lane >= o) x += u; }
        wsum[lane] = x;
    }
    __syncthreads();
    int run = v - s + (w > 0 ? wsum[w-1] : 0);
    #pragma unroll
    for(int i = 0; i < 16; i++){ g_rowptr[base + i] = run; run += c[i]; }
    if(t == 1023) g_rowptr[Nn] = run;
}

__global__ void k_fill(const int* __restrict__ ei){
    int e = blockIdx.x*blockDim.x + threadIdx.x;
    if(e >= Ne) return;
    int src = ei[e];
    int pos = g_rowptr[src] + atomicAdd(&g_cursor[src], 1);
    g_edst[pos] = ei[Ne + e];
    g_eidx[pos] = e;
}

// ---------------- h = leaky(LN(x)); also emit fp16 --------------------------------
__global__ void k_ln(const float* __restrict__ sc, const float* __restrict__ bi){
    int lane = threadIdx.x & 31, w = threadIdx.x >> 5;
    int n = blockIdx.x*8 + w;
    float v0 = g_x[n*64 + lane], v1 = g_x[n*64 + 32 + lane];
    float s = v0 + v1;
    #pragma unroll
    for(int o = 16; o; o >>= 1) s += __shfl_xor_sync(0xffffffffu, s, o);
    float mu = s * 0.015625f;
    float d0 = v0 - mu, d1 = v1 - mu;
    float q = d0*d0 + d1*d1;
    #pragma unroll
    for(int o = 16; o; o >>= 1) q += __shfl_xor_sync(0xffffffffu, q, o);
    float r = rsqrtf(q * 0.015625f + 1e-5f);
    float h0 = leaky(d0*r*sc[lane]      + bi[lane]);
    float h1 = leaky(d1*r*sc[32 + lane] + bi[32 + lane]);
    g_h[n*64 + lane]      = h0;
    g_h[n*64 + 32 + lane] = h1;
    g_h16[n*64 + lane]      = __float2half(h0);
    g_h16[n*64 + 32 + lane] = __float2half(h1);
}

// ---------------- mma helpers -------------------------------------------------------
#define BPAD 72
__device__ __forceinline__ void mma_bf16(float* c, const uint32_t* a, uint32_t b0, uint32_t b1){
    asm volatile(
        "mma.sync.aligned.m16n8k16.row.col.f32.bf16.bf16.f32 "
        "{%0,%1,%2,%3}, {%4,%5,%6,%7}, {%8,%9}, {%0,%1,%2,%3};"
        : "+f"(c[0]), "+f"(c[1]), "+f"(c[2]), "+f"(c[3])
        : "r"(a[0]), "r"(a[1]), "r"(a[2]), "r"(a[3]), "r"(b0), "r"(b1));
}
__device__ __forceinline__ void mma_f16(float* c, const uint32_t* a, uint32_t b0, uint32_t b1){
    asm volatile(
        "mma.sync.aligned.m16n8k16.row.col.f32.f16.f16.f32 "
        "{%0,%1,%2,%3}, {%4,%5,%6,%7}, {%8,%9}, {%0,%1,%2,%3};"
        : "+f"(c[0]), "+f"(c[1]), "+f"(c[2]), "+f"(c[3])
        : "r"(a[0]), "r"(a[1]), "r"(a[2]), "r"(a[3]), "r"(b0), "r"(b1));
}
__device__ __forceinline__ void ldsm_x4(uint32_t& r0, uint32_t& r1, uint32_t& r2, uint32_t& r3,
                                        uint32_t addr){
    asm volatile("ldmatrix.sync.aligned.m8n8.x4.shared.b16 {%0,%1,%2,%3}, [%4];"
        : "=r"(r0), "=r"(r1), "=r"(r2), "=r"(r3) : "r"(addr));
}

__device__ __forceinline__ void load_a_frags(const __nv_bfloat16* ph, const __nv_bfloat16* pl,
                                             int m0, int g, int tq,
                                             uint32_t ahi[4][4], uint32_t alo[4][4]){
    int r0 = (m0 + g)*64, r1 = (m0 + g + 8)*64;
    #pragma unroll
    for(int ks = 0; ks < 4; ks++){
        int c0 = ks*16 + 2*tq, c1 = c0 + 8;
        ahi[ks][0] = *(const uint32_t*)&ph[r0 + c0];
        ahi[ks][1] = *(const uint32_t*)&ph[r1 + c0];
        ahi[ks][2] = *(const uint32_t*)&ph[r0 + c1];
        ahi[ks][3] = *(const uint32_t*)&ph[r1 + c1];
        alo[ks][0] = *(const uint32_t*)&pl[r0 + c0];
        alo[ks][1] = *(const uint32_t*)&pl[r1 + c0];
        alo[ks][2] = *(const uint32_t*)&pl[r0 + c1];
        alo[ks][3] = *(const uint32_t*)&pl[r1 + c1];
    }
}

__device__ __forceinline__ void load_a_f16(const __half* p, int m0, int g, int tq,
                                           uint32_t a[4][4]){
    int r0 = (m0 + g)*64, r1 = (m0 + g + 8)*64;
    #pragma unroll
    for(int ks = 0; ks < 4; ks++){
        int c0 = ks*16 + 2*tq, c1 = c0 + 8;
        a[ks][0] = *(const uint32_t*)&p[r0 + c0];
        a[ks][1] = *(const uint32_t*)&p[r1 + c0];
        a[ks][2] = *(const uint32_t*)&p[r0 + c1];
        a[ks][3] = *(const uint32_t*)&p[r1 + c1];
    }
}

// ---------------- a = leaky(ea @ W1 + b1) via mma (unchanged, validated R6) --------
__global__ __launch_bounds__(256) void k_emlp_mma(int layer, const float* __restrict__ b1l){
    __shared__ __align__(16) __nv_bfloat16 Bh[128*BPAD];
    __shared__ __align__(16) __nv_bfloat16 Bl[128*BPAD];
    const __nv_bfloat16* w1h = g_w1t_hi + (size_t)layer*Hh*Dd;
    const __nv_bfloat16* w1l = g_w1t_lo + (size_t)layer*Hh*Dd;
    int tid = threadIdx.x, w = tid >> 5, lane = tid & 31;
    int g = lane >> 2, tq = lane & 3;
    int e0 = blockIdx.x * 128;
    int m0 = e0 + w*16;

    uint32_t ahi[4][4], alo[4][4];
    load_a_frags(g_ea_hi, g_ea_lo, m0, g, tq, ahi, alo);
    {
        const uint4* sh = (const uint4*)w1h;
        const uint4* sl = (const uint4*)w1l;
        #pragma unroll
        for(int i = 0; i < 4; i++){
            int idx = i*256 + tid;
            int f = idx >> 3, u = idx & 7;
            *(uint4*)&Bh[f*BPAD + u*8] = sh[idx];
            *(uint4*)&Bl[f*BPAD + u*8] = sl[idx];
        }
    }
    __syncthreads();

    float acc[16][4];
    #pragma unroll
    for(int j = 0; j < 16; j++)
        #pragma unroll
        for(int i = 0; i < 4; i++) acc[j][i] = 0.f;

    #pragma unroll
    for(int ks = 0; ks < 4; ks++){
        int cb0 = ks*16 + 2*tq, cb1 = cb0 + 8;
        #pragma unroll
        for(int j = 0; j < 16; j++){
            int row = (j*8 + g)*BPAD;
            uint32_t bh0 = *(const uint32_t*)&Bh[row + cb0];
            uint32_t bh1 = *(const uint32_t*)&Bh[row + cb1];
            uint32_t bl0 = *(const uint32_t*)&Bl[row + cb0];
            uint32_t bl1 = *(const uint32_t*)&Bl[row + cb1];
            mma_bf16(acc[j], ahi[ks], bh0, bh1);
            mma_bf16(acc[j], ahi[ks], bl0, bl1);
            mma_bf16(acc[j], alo[ks], bh0, bh1);
        }
    }

    float* a0 = g_a + (size_t)(m0 + g)*128;
    float* a1 = g_a + (size_t)(m0 + g + 8)*128;
    #pragma unroll
    for(int j = 0; j < 16; j++){
        int c = j*8 + 2*tq;
        float2 bb = *(const float2*)&b1l[c];
        *(float2*)&a0[c] = make_float2(leaky(acc[j][0] + bb.x), leaky(acc[j][1] + bb.y));
        *(float2*)&a1[c] = make_float2(leaky(acc[j][2] + bb.x), leaky(acc[j][3] + bb.y));
    }
}

// ---------------- Q via mma v4: fp16 A (1 term) x fp16 B hi/lo (2 terms) -----------
// Warp M-tile 32 rows (two m16 halves share each ldsm) -> LDSM/output halved,
// HMMA/output -33%. CTA = 256 rows. D staged per m-half through unioned buffer.
#define DPAD 72
__global__ __launch_bounds__(256, 2) void k_q_mma(int layer){
    __shared__ __align__(16) char smem_raw[18432];
    __half* Bh = (__half*)smem_raw;              // 64*BPAD*2 = 9216 B
    __half* Bl = (__half*)(smem_raw + 9216);
    __half* Ds = (__half*)smem_raw;              // 8 warps * 16 * DPAD * 2 = 18432 B
    const __half* w2h = g_w2t_hi + (size_t)layer*Hh*4096;
    const __half* w2l = g_w2t_lo + (size_t)layer*Hh*4096;
    int tid = threadIdx.x, w = tid >> 5, lane = tid & 31;
    int g = lane >> 2, tq = lane & 3;
    int n0 = blockIdx.x * 256;
    int m0 = n0 + w*32;

    uint32_t a0f[4][4], a1f[4][4];
    load_a_f16(g_h16, m0,      g, tq, a0f);
    load_a_f16(g_h16, m0 + 16, g, tq, a1f);

    // ldmatrix lane->address base: lanes 0-15 -> Bh, lanes 16-31 -> Bl
    int sel = lane >> 3, rw = lane & 7;
    uint32_t lds_base;
    {
        __half* arr = (sel < 2) ? Bh : Bl;
        lds_base = (uint32_t)__cvta_generic_to_shared(&arr[rw*BPAD + (sel & 1)*8]);
    }

    int kbase = blockIdx.y*8;
    uint4 pf_h0, pf_h1, pf_l0, pf_l1;
    {
        const uint4* sh = (const uint4*)(w2h + (size_t)kbase*4096);
        const uint4* sl = (const uint4*)(w2l + (size_t)kbase*4096);
        pf_h0 = sh[tid]; pf_h1 = sh[256 + tid];
        pf_l0 = sl[tid]; pf_l1 = sl[256 + tid];
    }
    int f0 = tid >> 3,         u0 = tid & 7;
    int f1 = (256 + tid) >> 3, u1 = tid & 7;

    __half* ds = Ds + w*16*DPAD;

    for(int kk = 0; kk < 8; kk++){
        int k = kbase + kk;
        __syncthreads();                       // prev D staging complete
        *(uint4*)&Bh[f0*BPAD + u0*8] = pf_h0;
        *(uint4*)&Bh[f1*BPAD + u1*8] = pf_h1;
        *(uint4*)&Bl[f0*BPAD + u0*8] = pf_l0;
        *(uint4*)&Bl[f1*BPAD + u1*8] = pf_l1;
        if(kk < 7){
            const uint4* sh = (const uint4*)(w2h + (size_t)(k + 1)*4096);
            const uint4* sl = (const uint4*)(w2l + (size_t)(k + 1)*4096);
            pf_h0 = sh[tid]; pf_h1 = sh[256 + tid];
            pf_l0 = sl[tid]; pf_l1 = sl[256 + tid];
        }
        __syncthreads();                       // B visible

        float acc0[8][4], acc1[8][4];
        #pragma unroll
        for(int j = 0; j < 8; j++)
            #pragma unroll
            for(int i = 0; i < 4; i++){ acc0[j][i] = 0.f; acc1[j][i] = 0.f; }

        #pragma unroll
        for(int ks = 0; ks < 4; ks++){
            #pragma unroll
            for(int j = 0; j < 8; j++){
                uint32_t bh0, bh1, bl0, bl1;
                ldsm_x4(bh0, bh1, bl0, bl1,
                        lds_base + (uint32_t)((j*8*BPAD + ks*16)*2));
                mma_f16(acc0[j], a0f[ks], bh0, bh1);
                mma_f16(acc0[j], a0f[ks], bl0, bl1);
                mma_f16(acc1[j], a1f[ks], bh0, bh1);
                mma_f16(acc1[j], a1f[ks], bl0, bl1);
            }
        }
        __syncthreads();                       // all warps done reading B

        // m-half 0: stage + coalesced store (rows m0..m0+15)
        #pragma unroll
        for(int j = 0; j < 8; j++){
            int c = j*8 + 2*tq;
            *(__half2*)&ds[g*DPAD + c]       = __floats2half2_rn(acc0[j][0], acc0[j][1]);
            *(__half2*)&ds[(g + 8)*DPAD + c] = __floats2half2_rn(acc0[j][2], acc0[j][3]);
        }
        __syncwarp();
        #pragma unroll
        for(int i = 0; i < 4; i++){
            int idx = i*32 + lane;
            int r = idx >> 3, u = idx & 7;
            uint4 v = *(const uint4*)&ds[r*DPAD + u*8];
            *(uint4*)(g_Q + ((size_t)(m0 + r)*128 + k)*64 + u*8) = v;
        }
        __syncwarp();
        // m-half 1: rows m0+16..m0+31 reuse the same staging slice
        #pragma unroll
        for(int j = 0; j < 8; j++){
            int c = j*8 + 2*tq;
            *(__half2*)&ds[g*DPAD + c]       = __floats2half2_rn(acc1[j][0], acc1[j][1]);
            *(__half2*)&ds[(g + 8)*DPAD + c] = __floats2half2_rn(acc1[j][2], acc1[j][3]);
        }
        __syncwarp();
        #pragma unroll
        for(int i = 0; i < 4; i++){
            int idx = i*32 + lane;
            int r = idx >> 3, u = idx & 7;
            uint4 v = *(const uint4*)&ds[r*DPAD + u*8];
            *(uint4*)(g_Q + ((size_t)(m0 + 16 + r)*128 + k)*64 + u*8) = v;
        }
    }
}

// ---------------- messages v3: fp16 smem Q, 8 edges/batch, f-pair lanes ------------
__global__ __launch_bounds__(256) void k_msg2(){
    __shared__ __align__(16) __half Qs[8192];   // [k][f] fp16, 16KB
    __shared__ float as[8][128];
    __shared__ float y2s[64];
    int n = blockIdx.x;
    int beg = g_rowptr[n], end = g_rowptr[n+1];
    if(beg == end) return;
    int tid = threadIdx.x;
    const uint4* qsrc = (const uint4*)(g_Q + (size_t)n*8192);
    uint4* qd = (uint4*)Qs;
    #pragma unroll
    for(int i = 0; i < 4; i++) qd[i*256 + tid] = qsrc[i*256 + tid];
    if(tid < 64) y2s[tid] = g_y2[n*64 + tid];
    __syncthreads();
    int g = tid >> 5, lane = tid & 31;
    const __half2* Q2 = (const __half2*)Qs;
    for(int base = beg; base < end; base += 8){
        #pragma unroll
        for(int i = 0; i < 4; i++){
            int idx = i*256 + tid;
            int el = idx >> 7, k = idx & 127;
            int j = base + el;
            if(j < end) as[el][k] = g_a[(size_t)g_eidx[j]*128 + k];
        }
        __syncthreads();
        int j = base + g;
        if(j < end){
            int dst = g_edst[j];
            float accx = y2s[2*lane], accy = y2s[2*lane + 1];
            #pragma unroll 8
            for(int k4 = 0; k4 < 128; k4 += 4){
                float4 av = *(const float4*)&as[g][k4];
                float2 q0 = __half22float2(Q2[(k4+0)*32 + lane]);
                float2 q1 = __half22float2(Q2[(k4+1)*32 + lane]);
                float2 q2 = __half22float2(Q2[(k4+2)*32 + lane]);
                float2 q3 = __half22float2(Q2[(k4+3)*32 + lane]);
                accx = fmaf(av.x, q0.x, accx); accy = fmaf(av.x, q0.y, accy);
                accx = fmaf(av.y, q1.x, accx); accy = fmaf(av.y, q1.y, accy);
                accx = fmaf(av.z, q2.x, accx); accy = fmaf(av.z, q2.y, accy);
                accx = fmaf(av.w, q3.x, accx); accy = fmaf(av.w, q3.y, accy);
            }
            atomicAdd(&g_num[dst*64 + 2*lane],     accx);
            atomicAdd(&g_num[dst*64 + 2*lane + 1], accy);
        }
        __syncthreads();
    }
}

// ---------------- shared 64x64 small GEMM with three epilogues ---------------------
__global__ __launch_bounds__(256) void k_nn64(const float* __restrict__ B,
                                              const float* __restrict__ bias,
                                              const float* __restrict__ cb,
                                              const int* __restrict__ batch,
                                              int mode){
    __shared__ float As[64][64];
    __shared__ float Bs[64][64];
    const float* A = (mode == 2) ? g_x : g_h;
    int tid = threadIdx.x;
    int n0 = blockIdx.x * 64;
    #pragma unroll
    for(int i = 0; i < 4; i++){
        int idx = i*256 + tid; int m = idx >> 4, d = (idx & 15) * 4;
        *(float4*)&As[m][d] = *(const float4*)&A[(size_t)(n0 + m)*64 + d];
        *(float4*)&Bs[m][d] = *(const float4*)&B[(size_t)m*64 + d];
    }
    __syncthreads();
    int tx = tid & 15, ty = tid >> 4;
    float acc[4][4];
    #pragma unroll
    for(int i = 0; i < 4; i++)
        #pragma unroll
        for(int j = 0; j < 4; j++) acc[i][j] = 0.f;

    #pragma unroll 4
    for(int d4 = 0; d4 < 64; d4 += 4){
        float4 a[4];
        #pragma unroll
        for(int i = 0; i < 4; i++) a[i] = *(float4*)&As[ty*4 + i][d4];
        #pragma unroll
        for(int dd = 0; dd < 4; dd++){
            float4 bv = *(float4*)&Bs[d4 + dd][tx*4];
            #pragma unroll
            for(int i = 0; i < 4; i++){
                float av = (dd==0)?a[i].x:(dd==1)?a[i].y:(dd==2)?a[i].z:a[i].w;
                acc[i][0] = fmaf(av, bv.x, acc[i][0]);
                acc[i][1] = fmaf(av, bv.y, acc[i][1]);
                acc[i][2] = fmaf(av, bv.z, acc[i][2]);
                acc[i][3] = fmaf(av, bv.w, acc[i][3]);
            }
        }
    }
    if(mode == 0){
        #pragma unroll
        for(int i = 0; i < 4; i++){
            float4 o; o.x = acc[i][0]; o.y = acc[i][1]; o.z = acc[i][2]; o.w = acc[i][3];
            *(float4*)&g_y2[(size_t)(n0 + ty*4 + i)*64 + tx*4] = o;
        }
    } else if(mode == 1){
        #pragma unroll
        for(int i = 0; i < 4; i++){
            int n = n0 + ty*4 + i;
            float inv = 1.f / fmaxf(g_deg[n], 1.f);
            #pragma unroll
            for(int j = 0; j < 4; j++){
                int idx = n*64 + tx*4 + j;
                float v = g_x[idx] + g_num[idx]*inv + acc[i][j] + cb[tx*4 + j];
                g_x[idx] = v;
                g_num[idx] = 0.f;
            }
        }
    } else {
        #pragma unroll
        for(int i = 0; i < 4; i++){
            int n = n0 + ty*4 + i;
            int b = batch[n];
            #pragma unroll
            for(int j = 0; j < 4; j++)
                atomicAdd(&g_pool[b*64 + tx*4 + j], acc[i][j] + bias[tx*4 + j]);
        }
    }
}

// ---------------- head -------------------------------------------------------------
__global__ void k_out(const float* __restrict__ oW, const float* __restrict__ ob,
                      float* __restrict__ out){
    __shared__ float p[64];
    int g = blockIdx.x, t = threadIdx.x;
    if(t < 64){
        float c = fmaxf(g_cnt[g], 1.f);
        p[t] = leaky(g_pool[g*64 + t] / c);
    }
    __syncthreads();
    float acc = ob[t];
    #pragma unroll 8
    for(int f = 0; f < 64; f++)
        acc = fmaf(p[f], oW[f*128 + t], acc);
    out[g*128 + t] = acc;
}

// ---------------- launch -------------------------------------------------------------
extern "C" void kernel_launch(void* const* d_in, const int* in_sizes, int n_in,
                              void* d_out, int out_size){
    const float* x    = (const float*)d_in[0];
    const int*   ei   = (const int*)  d_in[1];
    const float* ea   = (const float*)d_in[2];
    const int*   batch= (const int*)  d_in[3];
    const float* lns  = (const float*)d_in[4];
    const float* lnb  = (const float*)d_in[5];
    const float* W1   = (const float*)d_in[6];
    const float* b1   = (const float*)d_in[7];
    const float* W2   = (const float*)d_in[8];
    const float* b2   = (const float*)d_in[9];
    const float* root = (const float*)d_in[10];
    const float* cb   = (const float*)d_in[11];
    const float* dW   = (const float*)d_in[12];
    const float* db   = (const float*)d_in[13];
    const float* oW   = (const float*)d_in[14];
    const float* ob   = (const float*)d_in[15];
    float* out = (float*)d_out;

    dim3 gq(Nn/256, Hh/8);

    // Order chosen so launch index 3 (the one ncu captures) = k_q_mma(layer 0).
    k_prep<<<(Ne*Dd + 255)/256, 256>>>(W2, W1, ea);            // 0
    k_init<<<(Nn*Dd + 255)/256, 256>>>(x);                     // 1
    k_ln<<<Nn/8, 256>>>(lns, lnb);                             // 2
    k_q_mma<<<gq, 256>>>(0);                                   // 3  <- profiled
    k_degcnt<<<(Ne + 255)/256, 256>>>(ei, batch);              // 4
    k_scan<<<1, 1024>>>();                                     // 5
    k_fill<<<(Ne + 255)/256, 256>>>(ei);                       // 6
    k_emlp_mma<<<Ne/128, 256>>>(0, b1);                        // 7
    k_nn64<<<Nn/64, 256>>>(b2, nullptr, nullptr, nullptr, 0);  // 8: y2 = h@B2
    k_msg2<<<Nn, 256>>>();                                     // 9
    k_nn64<<<Nn/64, 256>>>(root, nullptr, cb, nullptr, 1);     // 10

    for(int l = 1; l < Ll; l++){
        k_ln<<<Nn/8, 256>>>(lns + l*64, lnb + l*64);
        k_emlp_mma<<<Ne/128, 256>>>(l, b1 + (size_t)l*128);
        k_nn64<<<Nn/64, 256>>>(b2 + (size_t)l*4096, nullptr, nullptr, nullptr, 0);
        k_q_mma<<<gq, 256>>>(l);
        k_msg2<<<Nn, 256>>>();
        k_nn64<<<Nn/64, 256>>>(root + (size_t)l*4096, nullptr, cb + (size_t)l*64, nullptr, 1);
    }

    k_nn64<<<Nn/64, 256>>>(dW, db, nullptr, batch, 2);  // dense + pool
    k_out<<<Gg, 128>>>(oW, ob, out);
}

// round 13
// speedup vs baseline: 2.0581x; 1.2052x over previous
#include <cuda_runtime.h>
#include <cuda_bf16.h>
#include <cuda_fp16.h>
#include <cstdint>

#define Nn 16384
#define Ne 65536
#define Dd 64
#define Hh 128
#define Ll 3
#define Gg 512
#define Oo 128

// ---------------- scratch -------------------------------------------------------
__device__ float g_x[Nn*Dd];
__device__ float g_h[Nn*Dd];
__device__ __half g_h16[Nn*Dd];                          // fp16 h for Q-GEMM A
__device__ float g_y2[Nn*Dd];
__device__ float g_a[(size_t)Ne*Hh];
__device__ __half g_Q[(size_t)Nn*Hh*Dd];                 // [n][k][f], fp16, 256 MB
__device__ __half g_w2t[(size_t)Ll*Hh*Dd*Dd];           // [l][k][f][d] fp16
__device__ __half g_w1t[(size_t)Ll*Hh*Dd];              // [l][f=128][d=64] fp16
__device__ __half g_ea16[(size_t)Ne*Dd];                 // edge_attr fp16
__device__ float g_num[Nn*Dd];
__device__ float g_deg[Nn];
__device__ float g_pool[Gg*Dd];
__device__ float g_cnt[Gg];
// CSR by src
__device__ int g_srccnt[Nn];
__device__ int g_cursor[Nn];
__device__ int g_rowptr[Nn + 1];
__device__ int g_edst[Ne];
__device__ int g_eidx[Ne];

__device__ __forceinline__ float leaky(float v){ return v > 0.f ? v : 0.01f*v; }

// ---------------- merged weight/edge prep (one launch slot) -----------------------
__global__ void k_prep(const float* __restrict__ W2, const float* __restrict__ W1,
                       const float* __restrict__ ea){
    int idx = blockIdx.x*blockDim.x + threadIdx.x;
    if(idx < Ne*Dd){
        g_ea16[idx] = __float2half(ea[idx]);
    }
    if(idx < Ll*Hh*Dd*Dd){
        int lk = idx >> 12;
        int d = (idx >> 6) & 63;
        int f = idx & 63;
        g_w2t[(size_t)lk*4096 + f*64 + d] = __float2half(W2[idx]);
    }
    if(idx < Ll*Dd*Hh){
        int l = idx >> 13;
        int d = (idx >> 7) & 63;
        int f = idx & 127;
        g_w1t[(size_t)l*Hh*Dd + f*64 + d] = __float2half(W1[idx]);
    }
}

// ---------------- init -----------------------------------------------------------
__global__ void k_init(const float* __restrict__ x){
    int i = blockIdx.x*blockDim.x + threadIdx.x;
    if(i < Nn*Dd){ g_x[i] = x[i]; g_num[i] = 0.f; }
    if(i < Gg*Dd) g_pool[i] = 0.f;
    if(i < Nn){ g_deg[i] = 0.f; g_srccnt[i] = 0; g_cursor[i] = 0; }
    if(i < Gg)  g_cnt[i] = 0.f;
}

__global__ void k_degcnt(const int* __restrict__ ei, const int* __restrict__ batch){
    int i = blockIdx.x*blockDim.x + threadIdx.x;
    if(i < Ne){
        atomicAdd(&g_deg[ei[Ne + i]], 1.f);
        atomicAdd(&g_srccnt[ei[i]], 1);
    }
    if(i < Nn) atomicAdd(&g_cnt[batch[i]], 1.f);
}

// single-block exclusive scan of g_srccnt -> g_rowptr
__global__ void k_scan(){
    __shared__ int wsum[32];
    int t = threadIdx.x;
    int base = t*16;
    int c[16]; int s = 0;
    #pragma unroll
    for(int i = 0; i < 16; i++){ c[i] = g_srccnt[base + i]; s += c[i]; }
    int lane = t & 31, w = t >> 5;
    int v = s;
    #pragma unroll
    for(int o = 1; o < 32; o <<= 1){ int u = __shfl_up_sync(~0u, v, o); if(lane >= o) v += u; }
    if(lane == 31) wsum[w] = v;
    __syncthreads();
    if(w == 0){
        int x = wsum[lane];
        #pragma unroll
        for(int o = 1; o < 32; o <<= 1){ int u = __shfl_up_sync(~0u, x, o); if(lane >= o) x += u; }
        wsum[lane] = x;
    }
    __syncthreads();
    int run = v - s + (w > 0 ? wsum[w-1] : 0);
    #pragma unroll
    for(int i = 0; i < 16; i++){ g_rowptr[base + i] = run; run += c[i]; }
    if(t == 1023) g_rowptr[Nn] = run;
}

__global__ void k_fill(const int* __restrict__ ei){
    int e = blockIdx.x*blockDim.x + threadIdx.x;
    if(e >= Ne) return;
    int src = ei[e];
    int pos = g_rowptr[src] + atomicAdd(&g_cursor[src], 1);
    g_edst[pos] = ei[Ne + e];
    g_eidx[pos] = e;
}

// ---------------- h = leaky(LN(x)); also emit fp16 --------------------------------
__global__ void k_ln(const float* __restrict__ sc, const float* __restrict__ bi){
    int lane = threadIdx.x & 31, w = threadIdx.x >> 5;
    int n = blockIdx.x*8 + w;
    float v0 = g_x[n*64 + lane], v1 = g_x[n*64 + 32 + lane];
    float s = v0 + v1;
    #pragma unroll
    for(int o = 16; o; o >>= 1) s += __shfl_xor_sync(0xffffffffu, s, o);
    float mu = s * 0.015625f;
    float d0 = v0 - mu, d1 = v1 - mu;
    float q = d0*d0 + d1*d1;
    #pragma unroll
    for(int o = 16; o; o >>= 1) q += __shfl_xor_sync(0xffffffffu, q, o);
    float r = rsqrtf(q * 0.015625f + 1e-5f);
    float h0 = leaky(d0*r*sc[lane]      + bi[lane]);
    float h1 = leaky(d1*r*sc[32 + lane] + bi[32 + lane]);
    g_h[n*64 + lane]      = h0;
    g_h[n*64 + 32 + lane] = h1;
    g_h16[n*64 + lane]      = __float2half(h0);
    g_h16[n*64 + 32 + lane] = __float2half(h1);
}

// ---------------- mma helpers -------------------------------------------------------
#define BPAD 72
__device__ __forceinline__ void mma_f16(float* c, const uint32_t* a, uint32_t b0, uint32_t b1){
    asm volatile(
        "mma.sync.aligned.m16n8k16.row.col.f32.f16.f16.f32 "
        "{%0,%1,%2,%3}, {%4,%5,%6,%7}, {%8,%9}, {%0,%1,%2,%3};"
        : "+f"(c[0]), "+f"(c[1]), "+f"(c[2]), "+f"(c[3])
        : "r"(a[0]), "r"(a[1]), "r"(a[2]), "r"(a[3]), "r"(b0), "r"(b1));
}
__device__ __forceinline__ void ldsm_x4(uint32_t& r0, uint32_t& r1, uint32_t& r2, uint32_t& r3,
                                        uint32_t addr){
    asm volatile("ldmatrix.sync.aligned.m8n8.x4.shared.b16 {%0,%1,%2,%3}, [%4];"
        : "=r"(r0), "=r"(r1), "=r"(r2), "=r"(r3) : "r"(addr));
}

__device__ __forceinline__ void load_a_f16(const __half* p, int m0, int g, int tq,
                                           uint32_t a[4][4]){
    int r0 = (m0 + g)*64, r1 = (m0 + g + 8)*64;
    #pragma unroll
    for(int ks = 0; ks < 4; ks++){
        int c0 = ks*16 + 2*tq, c1 = c0 + 8;
        a[ks][0] = *(const uint32_t*)&p[r0 + c0];
        a[ks][1] = *(const uint32_t*)&p[r1 + c0];
        a[ks][2] = *(const uint32_t*)&p[r0 + c1];
        a[ks][3] = *(const uint32_t*)&p[r1 + c1];
    }
}

// ---------------- a = leaky(ea @ W1 + b1), pure fp16 1-term ------------------------
__global__ __launch_bounds__(256) void k_emlp_mma(int layer, const float* __restrict__ b1l){
    __shared__ __align__(16) __half Bs[128*BPAD];
    const __half* w1 = g_w1t + (size_t)layer*Hh*Dd;
    int tid = threadIdx.x, w = tid >> 5, lane = tid & 31;
    int g = lane >> 2, tq = lane & 3;
    int e0 = blockIdx.x * 128;
    int m0 = e0 + w*16;

    uint32_t af[4][4];
    load_a_f16(g_ea16, m0, g, tq, af);
    {
        const uint4* sw = (const uint4*)w1;
        #pragma unroll
        for(int i = 0; i < 4; i++){
            int idx = i*256 + tid;
            int f = idx >> 3, u = idx & 7;
            *(uint4*)&Bs[f*BPAD + u*8] = sw[idx];
        }
    }
    __syncthreads();

    float acc[16][4];
    #pragma unroll
    for(int j = 0; j < 16; j++)
        #pragma unroll
        for(int i = 0; i < 4; i++) acc[j][i] = 0.f;

    #pragma unroll
    for(int ks = 0; ks < 4; ks++){
        int cb0 = ks*16 + 2*tq, cb1 = cb0 + 8;
        #pragma unroll
        for(int j = 0; j < 16; j++){
            int row = (j*8 + g)*BPAD;
            uint32_t b0 = *(const uint32_t*)&Bs[row + cb0];
            uint32_t b1 = *(const uint32_t*)&Bs[row + cb1];
            mma_f16(acc[j], af[ks], b0, b1);
        }
    }

    float* a0 = g_a + (size_t)(m0 + g)*128;
    float* a1 = g_a + (size_t)(m0 + g + 8)*128;
    #pragma unroll
    for(int j = 0; j < 16; j++){
        int c = j*8 + 2*tq;
        float2 bb = *(const float2*)&b1l[c];
        *(float2*)&a0[c] = make_float2(leaky(acc[j][0] + bb.x), leaky(acc[j][1] + bb.y));
        *(float2*)&a1[c] = make_float2(leaky(acc[j][2] + bb.x), leaky(acc[j][3] + bb.y));
    }
}

// ---------------- Q via mma v5: pure fp16 1-term; ldsm.x4 fetches 2 ks-steps -------
// Warp M-tile 32 rows. Per k-slice per warp: 16 LDSM, 64 HMMA (halved from R12).
// B buffer 9216B unions with D staging (18432B): never live simultaneously.
#define DPAD 72
__global__ __launch_bounds__(256, 2) void k_q_mma(int layer){
    __shared__ __align__(16) char smem_raw[18432];
    __half* Bh = (__half*)smem_raw;              // 64*BPAD*2 = 9216 B
    __half* Ds = (__half*)smem_raw;              // 8 warps * 16 * DPAD * 2 = 18432 B
    const __half* w2 = g_w2t + (size_t)layer*Hh*4096;
    int tid = threadIdx.x, w = tid >> 5, lane = tid & 31;
    int g = lane >> 2, tq = lane & 3;
    int n0 = blockIdx.x * 256;
    int m0 = n0 + w*32;

    uint32_t a0f[4][4], a1f[4][4];
    load_a_f16(g_h16, m0,      g, tq, a0f);
    load_a_f16(g_h16, m0 + 16, g, tq, a1f);

    // ldsm.x4 lane->address: sel = lane>>3 picks (ks-step parity, d-offset):
    // sel0: ks+0,d+0  sel1: ks+0,d+8  sel2: ks+1,d+0  sel3: ks+1,d+8  (all in Bh)
    int sel = lane >> 3, rw = lane & 7;
    uint32_t lds_base = (uint32_t)__cvta_generic_to_shared(
        &Bh[rw*BPAD + (sel & 1)*8 + (sel >> 1)*16]);

    int kbase = blockIdx.y*8;
    uint4 pf0, pf1;
    {
        const uint4* sw = (const uint4*)(w2 + (size_t)kbase*4096);
        pf0 = sw[tid]; pf1 = sw[256 + tid];
    }
    int f0 = tid >> 3,         u0 = tid & 7;
    int f1 = (256 + tid) >> 3, u1 = tid & 7;

    __half* ds = Ds + w*16*DPAD;

    for(int kk = 0; kk < 8; kk++){
        int k = kbase + kk;
        __syncthreads();                       // prev D staging complete
        *(uint4*)&Bh[f0*BPAD + u0*8] = pf0;
        *(uint4*)&Bh[f1*BPAD + u1*8] = pf1;
        if(kk < 7){
            const uint4* sw = (const uint4*)(w2 + (size_t)(k + 1)*4096);
            pf0 = sw[tid]; pf1 = sw[256 + tid];
        }
        __syncthreads();                       // B visible

        float acc0[8][4], acc1[8][4];
        #pragma unroll
        for(int j = 0; j < 8; j++)
            #pragma unroll
            for(int i = 0; i < 4; i++){ acc0[j][i] = 0.f; acc1[j][i] = 0.f; }

        #pragma unroll
        for(int ksp = 0; ksp < 2; ksp++){      // each ldsm covers ks=2ksp, 2ksp+1
            #pragma unroll
            for(int j = 0; j < 8; j++){
                uint32_t b00, b01, b10, b11;
                ldsm_x4(b00, b01, b10, b11,
                        lds_base + (uint32_t)((j*8*BPAD + ksp*32)*2));
                mma_f16(acc0[j], a0f[2*ksp],     b00, b01);
                mma_f16(acc0[j], a0f[2*ksp + 1], b10, b11);
                mma_f16(acc1[j], a1f[2*ksp],     b00, b01);
                mma_f16(acc1[j], a1f[2*ksp + 1], b10, b11);
            }
        }
        __syncthreads();                       // all warps done reading B

        // m-half 0: stage + coalesced store (rows m0..m0+15)
        #pragma unroll
        for(int j = 0; j < 8; j++){
            int c = j*8 + 2*tq;
            *(__half2*)&ds[g*DPAD + c]       = __floats2half2_rn(acc0[j][0], acc0[j][1]);
            *(__half2*)&ds[(g + 8)*DPAD + c] = __floats2half2_rn(acc0[j][2], acc0[j][3]);
        }
        __syncwarp();
        #pragma unroll
        for(int i = 0; i < 4; i++){
            int idx = i*32 + lane;
            int r = idx >> 3, u = idx & 7;
            uint4 v = *(const uint4*)&ds[r*DPAD + u*8];
            *(uint4*)(g_Q + ((size_t)(m0 + r)*128 + k)*64 + u*8) = v;
        }
        __syncwarp();
        // m-half 1: rows m0+16..m0+31
        #pragma unroll
        for(int j = 0; j < 8; j++){
            int c = j*8 + 2*tq;
            *(__half2*)&ds[g*DPAD + c]       = __floats2half2_rn(acc1[j][0], acc1[j][1]);
            *(__half2*)&ds[(g + 8)*DPAD + c] = __floats2half2_rn(acc1[j][2], acc1[j][3]);
        }
        __syncwarp();
        #pragma unroll
        for(int i = 0; i < 4; i++){
            int idx = i*32 + lane;
            int r = idx >> 3, u = idx & 7;
            uint4 v = *(const uint4*)&ds[r*DPAD + u*8];
            *(uint4*)(g_Q + ((size_t)(m0 + 16 + r)*128 + k)*64 + u*8) = v;
        }
    }
}

// ---------------- messages v3: fp16 smem Q, 8 edges/batch, f-pair lanes ------------
__global__ __launch_bounds__(256) void k_msg2(){
    __shared__ __align__(16) __half Qs[8192];   // [k][f] fp16, 16KB
    __shared__ float as[8][128];
    __shared__ float y2s[64];
    int n = blockIdx.x;
    int beg = g_rowptr[n], end = g_rowptr[n+1];
    if(beg == end) return;
    int tid = threadIdx.x;
    const uint4* qsrc = (const uint4*)(g_Q + (size_t)n*8192);
    uint4* qd = (uint4*)Qs;
    #pragma unroll
    for(int i = 0; i < 4; i++) qd[i*256 + tid] = qsrc[i*256 + tid];
    if(tid < 64) y2s[tid] = g_y2[n*64 + tid];
    __syncthreads();
    int g = tid >> 5, lane = tid & 31;
    const __half2* Q2 = (const __half2*)Qs;
    for(int base = beg; base < end; base += 8){
        #pragma unroll
        for(int i = 0; i < 4; i++){
            int idx = i*256 + tid;
            int el = idx >> 7, k = idx & 127;
            int j = base + el;
            if(j < end) as[el][k] = g_a[(size_t)g_eidx[j]*128 + k];
        }
        __syncthreads();
        int j = base + g;
        if(j < end){
            int dst = g_edst[j];
            float accx = y2s[2*lane], accy = y2s[2*lane + 1];
            #pragma unroll 8
            for(int k4 = 0; k4 < 128; k4 += 4){
                float4 av = *(const float4*)&as[g][k4];
                float2 q0 = __half22float2(Q2[(k4+0)*32 + lane]);
                float2 q1 = __half22float2(Q2[(k4+1)*32 + lane]);
                float2 q2 = __half22float2(Q2[(k4+2)*32 + lane]);
                float2 q3 = __half22float2(Q2[(k4+3)*32 + lane]);
                accx = fmaf(av.x, q0.x, accx); accy = fmaf(av.x, q0.y, accy);
                accx = fmaf(av.y, q1.x, accx); accy = fmaf(av.y, q1.y, accy);
                accx = fmaf(av.z, q2.x, accx); accy = fmaf(av.z, q2.y, accy);
                accx = fmaf(av.w, q3.x, accx); accy = fmaf(av.w, q3.y, accy);
            }
            atomicAdd(&g_num[dst*64 + 2*lane],     accx);
            atomicAdd(&g_num[dst*64 + 2*lane + 1], accy);
        }
        __syncthreads();
    }
}

// ---------------- shared 64x64 small GEMM with three epilogues ---------------------
__global__ __launch_bounds__(256) void k_nn64(const float* __restrict__ B,
                                              const float* __restrict__ bias,
                                              const float* __restrict__ cb,
                                              const int* __restrict__ batch,
                                              int mode){
    __shared__ float As[64][64];
    __shared__ float Bs[64][64];
    const float* A = (mode == 2) ? g_x : g_h;
    int tid = threadIdx.x;
    int n0 = blockIdx.x * 64;
    #pragma unroll
    for(int i = 0; i < 4; i++){
        int idx = i*256 + tid; int m = idx >> 4, d = (idx & 15) * 4;
        *(float4*)&As[m][d] = *(const float4*)&A[(size_t)(n0 + m)*64 + d];
        *(float4*)&Bs[m][d] = *(const float4*)&B[(size_t)m*64 + d];
    }
    __syncthreads();
    int tx = tid & 15, ty = tid >> 4;
    float acc[4][4];
    #pragma unroll
    for(int i = 0; i < 4; i++)
        #pragma unroll
        for(int j = 0; j < 4; j++) acc[i][j] = 0.f;

    #pragma unroll 4
    for(int d4 = 0; d4 < 64; d4 += 4){
        float4 a[4];
        #pragma unroll
        for(int i = 0; i < 4; i++) a[i] = *(float4*)&As[ty*4 + i][d4];
        #pragma unroll
        for(int dd = 0; dd < 4; dd++){
            float4 bv = *(float4*)&Bs[d4 + dd][tx*4];
            #pragma unroll
            for(int i = 0; i < 4; i++){
                float av = (dd==0)?a[i].x:(dd==1)?a[i].y:(dd==2)?a[i].z:a[i].w;
                acc[i][0] = fmaf(av, bv.x, acc[i][0]);
                acc[i][1] = fmaf(av, bv.y, acc[i][1]);
                acc[i][2] = fmaf(av, bv.z, acc[i][2]);
                acc[i][3] = fmaf(av, bv.w, acc[i][3]);
            }
        }
    }
    if(mode == 0){
        #pragma unroll
        for(int i = 0; i < 4; i++){
            float4 o; o.x = acc[i][0]; o.y = acc[i][1]; o.z = acc[i][2]; o.w = acc[i][3];
            *(float4*)&g_y2[(size_t)(n0 + ty*4 + i)*64 + tx*4] = o;
        }
    } else if(mode == 1){
        #pragma unroll
        for(int i = 0; i < 4; i++){
            int n = n0 + ty*4 + i;
            float inv = 1.f / fmaxf(g_deg[n], 1.f);
            #pragma unroll
            for(int j = 0; j < 4; j++){
                int idx = n*64 + tx*4 + j;
                float v = g_x[idx] + g_num[idx]*inv + acc[i][j] + cb[tx*4 + j];
                g_x[idx] = v;
                g_num[idx] = 0.f;
            }
        }
    } else {
        #pragma unroll
        for(int i = 0; i < 4; i++){
            int n = n0 + ty*4 + i;
            int b = batch[n];
            #pragma unroll
            for(int j = 0; j < 4; j++)
                atomicAdd(&g_pool[b*64 + tx*4 + j], acc[i][j] + bias[tx*4 + j]);
        }
    }
}

// ---------------- head -------------------------------------------------------------
__global__ void k_out(const float* __restrict__ oW, const float* __restrict__ ob,
                      float* __restrict__ out){
    __shared__ float p[64];
    int g = blockIdx.x, t = threadIdx.x;
    if(t < 64){
        float c = fmaxf(g_cnt[g], 1.f);
        p[t] = leaky(g_pool[g*64 + t] / c);
    }
    __syncthreads();
    float acc = ob[t];
    #pragma unroll 8
    for(int f = 0; f < 64; f++)
        acc = fmaf(p[f], oW[f*128 + t], acc);
    out[g*128 + t] = acc;
}

// ---------------- launch -------------------------------------------------------------
extern "C" void kernel_launch(void* const* d_in, const int* in_sizes, int n_in,
                              void* d_out, int out_size){
    const float* x    = (const float*)d_in[0];
    const int*   ei   = (const int*)  d_in[1];
    const float* ea   = (const float*)d_in[2];
    const int*   batch= (const int*)  d_in[3];
    const float* lns  = (const float*)d_in[4];
    const float* lnb  = (const float*)d_in[5];
    const float* W1   = (const float*)d_in[6];
    const float* b1   = (const float*)d_in[7];
    const float* W2   = (const float*)d_in[8];
    const float* b2   = (const float*)d_in[9];
    const float* root = (const float*)d_in[10];
    const float* cb   = (const float*)d_in[11];
    const float* dW   = (const float*)d_in[12];
    const float* db   = (const float*)d_in[13];
    const float* oW   = (const float*)d_in[14];
    const float* ob   = (const float*)d_in[15];
    float* out = (float*)d_out;

    dim3 gq(Nn/256, Hh/8);

    // Order chosen so launch index 3 (the one ncu captures) = k_q_mma(layer 0).
    k_prep<<<(Ne*Dd + 255)/256, 256>>>(W2, W1, ea);            // 0
    k_init<<<(Nn*Dd + 255)/256, 256>>>(x);                     // 1
    k_ln<<<Nn/8, 256>>>(lns, lnb);                             // 2
    k_q_mma<<<gq, 256>>>(0);                                   // 3  <- profiled
    k_degcnt<<<(Ne + 255)/256, 256>>>(ei, batch);              // 4
    k_scan<<<1, 1024>>>();                                     // 5
    k_fill<<<(Ne + 255)/256, 256>>>(ei);                       // 6
    k_emlp_mma<<<Ne/128, 256>>>(0, b1);                        // 7
    k_nn64<<<Nn/64, 256>>>(b2, nullptr, nullptr, nullptr, 0);  // 8: y2 = h@B2
    k_msg2<<<Nn, 256>>>();                                     // 9
    k_nn64<<<Nn/64, 256>>>(root, nullptr, cb, nullptr, 1);     // 10

    for(int l = 1; l < Ll; l++){
        k_ln<<<Nn/8, 256>>>(lns + l*64, lnb + l*64);
        k_emlp_mma<<<Ne/128, 256>>>(l, b1 + (size_t)l*128);
        k_nn64<<<Nn/64, 256>>>(b2 + (size_t)l*4096, nullptr, nullptr, nullptr, 0);
        k_q_mma<<<gq, 256>>>(l);
        k_msg2<<<Nn, 256>>>();
        k_nn64<<<Nn/64, 256>>>(root + (size_t)l*4096, nullptr, cb + (size_t)l*64, nullptr, 1);
    }

    k_nn64<<<Nn/64, 256>>>(dW, db, nullptr, batch, 2);  // dense + pool
    k_out<<<Gg, 128>>>(oW, ob, out);
}